// round 9
// baseline (speedup 1.0000x reference)
#include <cuda_runtime.h>
#include <cuda_bf16.h>
#include <math.h>
#include <float.h>
#include <stdint.h>

// Problem constants
#define BQ      4
#define SEQ     4096
#define DMODEL  2048
#define NH      16
#define DN      128
#define DRD     64
#define DVD     128
#define QLAT    512
#define KVLAT   512
#define MROWS   (BQ*SEQ)          // 16384
#define QW      (NH*(DN+DRD))     // 3072
#define KVAW    (KVLAT+DRD)       // 576
#define KVAP    640               // padded N for wkv_a pack
#define KVBW    (NH*(DN+DVD))     // 4096
#define OW      (NH*DVD)          // 2048
#define SCALE_F 0.07216878364870323f

// ---------------- scratch ----------------
__device__ float g_q   [MROWS*QW];
__device__ float g_kvb [MROWS*KVBW];
__device__ float g_kpe [MROWS*DRD];
__device__ float g_kperaw[MROWS*DRD];
__device__ unsigned int g_eta_enc[256];
__device__ float g_eta[256];
// fragment-packed operands (tf32-rounded)
__device__ float g_xpk   [MROWS*DMODEL];
__device__ float g_qlatpk[MROWS*QLAT];
__device__ float g_kvapk [MROWS*KVLAT];
__device__ float g_attnpk[MROWS*OW];
__device__ float g_wqapk [QLAT*DMODEL];
__device__ float g_wqbpk [QW*QLAT];
__device__ float g_wkapk [KVAP*DMODEL];
__device__ float g_wkbpk [KVBW*KVLAT];
__device__ float g_wopk  [DMODEL*OW];

// ---------------- helpers ----------------
__device__ __forceinline__ float silu_f(float x) { return x / (1.0f + expf(-x)); }

__device__ __forceinline__ unsigned encf(float f) {
    unsigned u = __float_as_uint(f);
    return (u & 0x80000000u) ? ~u : (u | 0x80000000u);
}
__device__ __forceinline__ float decf(unsigned u) {
    return (u & 0x80000000u) ? __uint_as_float(u ^ 0x80000000u) : __uint_as_float(~u);
}
__device__ __forceinline__ uint32_t smem_u32(const void* p) {
    uint32_t a;
    asm("{ .reg .u64 t; cvta.to.shared.u64 t, %1; cvt.u32.u64 %0, t; }" : "=r"(a) : "l"(p));
    return a;
}
__device__ __forceinline__ void cpasync16(uint32_t dst, const void* src) {
    asm volatile("cp.async.cg.shared.global [%0], [%1], 16;" :: "r"(dst), "l"(src));
}
__device__ __forceinline__ void cp_commit() { asm volatile("cp.async.commit_group;" ::: "memory"); }
__device__ __forceinline__ void cp_wait1()  { asm volatile("cp.async.wait_group 1;"  ::: "memory"); }

__device__ __forceinline__ uint32_t f2tf(float f) {
    uint32_t r;
    asm("cvt.rna.tf32.f32 %0, %1;" : "=r"(r) : "f"(f));
    return r;
}
__device__ __forceinline__ float f2tff(float f) { return __uint_as_float(f2tf(f)); }

__device__ __forceinline__ void mma8(float* d, const uint32_t* a, const uint32_t* b) {
    asm volatile("mma.sync.aligned.m16n8k8.row.col.f32.tf32.tf32.f32 "
        "{%0,%1,%2,%3},{%4,%5,%6,%7},{%8,%9},{%0,%1,%2,%3};"
        : "+f"(d[0]), "+f"(d[1]), "+f"(d[2]), "+f"(d[3])
        : "r"(a[0]), "r"(a[1]), "r"(a[2]), "r"(a[3]), "r"(b[0]), "r"(b[1]));
}

// packed-A element index: m,k -> offset (Kt = K/8 tiles)
__device__ __forceinline__ size_t a_pk_idx(int m, int k, int Kt) {
    int tm = m >> 4, rr = m & 15, lr = rr & 7, hi = rr >> 3;
    int tk = k >> 3, k7 = k & 7, qk = (k7 >> 2) << 1, lc = k7 & 3;
    return ((size_t)tm * Kt + tk) * 128 + (lr * 4 + lc) * 4 + qk + hi;
}

// ---------------- pack kernels (round to tf32) ----------------
__global__ void pack_a_k(const float* __restrict__ src, float* __restrict__ dst, int Kt, int ld, int n) {
    int o = blockIdx.x * blockDim.x + threadIdx.x;
    if (o >= n) return;
    int tile = o >> 7, l4q = o & 127, l = l4q >> 2, q = l4q & 3;
    int tm = tile / Kt, tk = tile % Kt;
    int r = tm * 16 + (q & 1) * 8 + (l >> 2);
    int k = tk * 8 + (q >> 1) * 4 + (l & 3);
    dst[o] = f2tff(src[(size_t)r * ld + k]);
}

__global__ void pack_b_k(const float* __restrict__ src, float* __restrict__ dst, int Kt, int ld, int N, int n) {
    int o = blockIdx.x * blockDim.x + threadIdx.x;
    if (o >= n) return;
    int tile = o >> 6, lq = o & 63, l = lq >> 1, q = lq & 1;
    int tn = tile / Kt, tk = tile % Kt;
    int nr = tn * 8 + (l >> 2);
    int k = tk * 8 + q * 4 + (l & 3);
    dst[o] = (nr < N) ? f2tff(src[(size_t)nr * ld + k]) : 0.0f;
}

// ---------------- packed tf32 GEMM: C[M,N] = A[M,K] @ B[N,K]^T ----------------
// BM=256, BN=128, BK=32, 256 threads (8 warps, 64x64 warp tile), 3 stages, 1 CTA/SM.
// EPI: 0=plain  1=packed-A out(Kt=64)  2=Q silu/rope + eta  3=kva packed + kperaw  4=kvb silu + eta
#define STAGE_B 49152
#define GEMM_SMEM (3*STAGE_B)     // 144 KB

template<int EPI>
__global__ void __launch_bounds__(256, 1)
gemm_pk(const float* __restrict__ A, const float* __restrict__ B, float* __restrict__ C,
        float* __restrict__ C2, int N, int K, const float* __restrict__ fc)
{
    extern __shared__ float sm[];
    uint32_t sb = smem_u32(sm);
    int Kt = K >> 3;

    int tid  = threadIdx.x;
    int bm   = blockIdx.y * 256;
    int bn   = blockIdx.x * 128;
    int wid  = tid >> 5, lane = tid & 31;
    int wm   = (wid >> 1) * 64;      // 4 warp rows
    int wn   = (wid & 1) * 64;       // 2 warp cols
    int lr   = lane >> 2, lc = lane & 3;

    float acc[4][8][4];
#pragma unroll
    for (int t = 0; t < 4; t++)
#pragma unroll
        for (int j = 0; j < 8; j++)
#pragma unroll
            for (int v = 0; v < 4; v++) acc[t][j][v] = 0.f;

    auto loadStage = [&](int s, int ko) {
        uint32_t abase = sb + s * STAGE_B;
        uint32_t bbase = abase + 32768;
        int kt0 = ko >> 3;
#pragma unroll
        for (int j = 0; j < 8; j++) {
            int idx = j * 256 + tid;
            int tm = idx >> 7, u = idx & 127;
            const float* src = A + ((size_t)(bm / 16 + tm) * Kt + kt0) * 128 + u * 4;
            cpasync16(abase + tm * 2048 + u * 16, src);
        }
#pragma unroll
        for (int j = 0; j < 4; j++) {
            int idx = j * 256 + tid;
            int tn = idx >> 6, u = idx & 63;
            const float* src = B + ((size_t)(bn / 8 + tn) * Kt + kt0) * 64 + u * 4;
            cpasync16(bbase + tn * 1024 + u * 16, src);
        }
    };

    int nk = K / 32;
    loadStage(0, 0);  cp_commit();
    loadStage(1, 32); cp_commit();

    for (int i = 0; i < nk; i++) {
        int s = i % 3;
        cp_wait1();
        __syncthreads();
        if (i + 2 < nk) loadStage((i + 2) % 3, (i + 2) * 32);
        cp_commit();

        const float* as = sm + s * (STAGE_B/4);
        const float* bs = as + 8192;
#pragma unroll
        for (int ks = 0; ks < 4; ks++) {
            uint32_t af[4][4], bf[8][2];
#pragma unroll
            for (int t = 0; t < 4; t++) {
                float4 v = *(const float4*)(as + ((wm >> 4) + t) * 512 + ks * 128 + lane * 4);
                af[t][0] = __float_as_uint(v.x); af[t][1] = __float_as_uint(v.y);
                af[t][2] = __float_as_uint(v.z); af[t][3] = __float_as_uint(v.w);
            }
#pragma unroll
            for (int j = 0; j < 8; j++) {
                float2 v = *(const float2*)(bs + ((wn >> 3) + j) * 256 + ks * 64 + lane * 2);
                bf[j][0] = __float_as_uint(v.x); bf[j][1] = __float_as_uint(v.y);
            }
#pragma unroll
            for (int t = 0; t < 4; t++)
#pragma unroll
                for (int j = 0; j < 8; j++)
                    mma8(acc[t][j], af[t], bf[j]);
        }
    }

    // epilogue (+ optional fused eta max)
    float mnope = -FLT_MAX, mpe = -FLT_MAX;
#pragma unroll
    for (int t = 0; t < 4; t++) {
        int row0 = bm + wm + t * 16 + lr;
#pragma unroll
        for (int j = 0; j < 8; j++) {
            int col = bn + wn + j * 8 + lc * 2;
            float v0 = acc[t][j][0], v1 = acc[t][j][1], v2 = acc[t][j][2], v3 = acc[t][j][3];
            if (EPI == 0) {
                *(float2*)&C[(size_t)row0 * N + col]       = make_float2(v0, v1);
                *(float2*)&C[(size_t)(row0 + 8) * N + col] = make_float2(v2, v3);
            } else if (EPI == 1) {
                int tm = (bm + wm + t * 16) >> 4;
                int tk = col >> 3;
                int lp = lr * 4 + ((col & 7) & 3);
                int qk = (col & 4) >> 1;
                size_t base = ((size_t)tm * 64 + tk) * 128;
                *(float2*)&C[base + lp * 4 + qk]       = make_float2(f2tff(v0), f2tff(v2));
                *(float2*)&C[base + (lp + 1) * 4 + qk] = make_float2(f2tff(v1), f2tff(v3));
            } else if (EPI == 2) {
                int d = col % 192;
                if (d < DN) {
                    v0 = silu_f(v0); v1 = silu_f(v1); v2 = silu_f(v2); v3 = silu_f(v3);
                    mnope = fmaxf(mnope, fmaxf(fmaxf(v0, v1), fmaxf(v2, v3)));
                } else {
                    int p = (d - DN) >> 1;
                    int s0 = row0 & (SEQ - 1), s1 = (row0 + 8) & (SEQ - 1);
                    float c0 = fc[s0*64 + p*2], n0 = fc[s0*64 + p*2 + 1];
                    float c1 = fc[s1*64 + p*2], n1 = fc[s1*64 + p*2 + 1];
                    float r0 = v0*c0 - v1*n0, i0 = v0*n0 + v1*c0;
                    float r1 = v2*c1 - v3*n1, i1 = v2*n1 + v3*c1;
                    v0 = silu_f(r0); v1 = silu_f(i0); v2 = silu_f(r1); v3 = silu_f(i1);
                    mpe = fmaxf(mpe, fmaxf(fmaxf(v0, v1), fmaxf(v2, v3)));
                }
                *(float2*)&C[(size_t)row0 * N + col]       = make_float2(v0, v1);
                *(float2*)&C[(size_t)(row0 + 8) * N + col] = make_float2(v2, v3);
            } else if (EPI == 3) {
                if (col < KVLAT) {
                    int tm = (bm + wm + t * 16) >> 4;
                    int tk = col >> 3;
                    int lp = lr * 4 + ((col & 7) & 3);
                    int qk = (col & 4) >> 1;
                    size_t base = ((size_t)tm * 64 + tk) * 128;
                    *(float2*)&C[base + lp * 4 + qk]       = make_float2(f2tff(v0), f2tff(v2));
                    *(float2*)&C[base + (lp + 1) * 4 + qk] = make_float2(f2tff(v1), f2tff(v3));
                } else if (col < KVAW) {
                    *(float2*)&C2[(size_t)row0 * DRD + col - KVLAT]       = make_float2(v0, v1);
                    *(float2*)&C2[(size_t)(row0 + 8) * DRD + col - KVLAT] = make_float2(v2, v3);
                }
            } else if (EPI == 4) {
                int d = col % 256;
                if (d < DN) {
                    v0 = silu_f(v0); v1 = silu_f(v1); v2 = silu_f(v2); v3 = silu_f(v3);
                    mnope = fmaxf(mnope, fmaxf(fmaxf(v0, v1), fmaxf(v2, v3)));
                }
                *(float2*)&C[(size_t)row0 * N + col]       = make_float2(v0, v1);
                *(float2*)&C[(size_t)(row0 + 8) * N + col] = make_float2(v2, v3);
            }
        }
    }

    if (EPI == 2 || EPI == 4) {
        // CTA covers rows [bm, bm+256) = exactly eta group bm/256
        __syncthreads();
        sm[tid] = mnope;
        if (EPI == 2) sm[256 + tid] = mpe;
        __syncthreads();
        for (int st = 128; st > 0; st >>= 1) {
            if (tid < st) {
                sm[tid] = fmaxf(sm[tid], sm[tid + st]);
                if (EPI == 2) sm[256 + tid] = fmaxf(sm[256 + tid], sm[256 + tid + st]);
            }
            __syncthreads();
        }
        if (tid == 0) {
            int grp = bm >> 8;
            atomicMax(&g_eta_enc[(EPI == 2 ? 0 : 1) * 64 + grp], encf(sm[0]));
            if (EPI == 2) atomicMax(&g_eta_enc[2 * 64 + grp], encf(sm[256]));
        }
    }
}

// ---------------- rope+silu for k_pe + fused eta(t3) ----------------
__global__ void rope_silu_kpe_k(const float* __restrict__ fc) {
    __shared__ float red[256];
    int i = blockIdx.x * blockDim.x + threadIdx.x;
    int m = i >> 5;
    int p = i & 31;
    int s = m & (SEQ - 1);
    float c = fc[s*64 + p*2 + 0];
    float sn = fc[s*64 + p*2 + 1];
    float xr = g_kperaw[(size_t)m*DRD + 2*p];
    float xi = g_kperaw[(size_t)m*DRD + 2*p + 1];
    float y0 = silu_f(xr*c - xi*sn);
    float y1 = silu_f(xr*sn + xi*c);
    g_kpe[(size_t)m*DRD + 2*p]     = y0;
    g_kpe[(size_t)m*DRD + 2*p + 1] = y1;
    red[threadIdx.x] = fmaxf(y0, y1);
    __syncthreads();
    for (int st = 128; st > 0; st >>= 1) {
        if (threadIdx.x < st) red[threadIdx.x] = fmaxf(red[threadIdx.x], red[threadIdx.x + st]);
        __syncthreads();
    }
    if (threadIdx.x == 0) {
        int grp = blockIdx.x >> 5;      // 8 rows per block, 256 rows per group
        atomicMax(&g_eta_enc[3*64 + grp], encf(red[0]));
    }
}

// ---------------- eta ----------------
__global__ void eta_init_k() {
    if (threadIdx.x < 256) g_eta_enc[threadIdx.x] = 0u;
}

__global__ void eta_fin_k() {
    int i = threadIdx.x;
    if (i < 256) {
        float m = decf(g_eta_enc[i]);
        if (m == 0.0f) m = 1e-6f;
        g_eta[i] = fminf(10.0f / m, 1.0f);
    }
}

// ---------------- block attention (output packed for GEMM5 A) ----------------
__global__ void __launch_bounds__(256) attn_kernel() {
    __shared__ float sA[64*65];
    __shared__ float sB[64*65];
    int bnb = blockIdx.x;
    int h   = blockIdx.y;
    int b = bnb >> 6, n = bnb & 63;
    int m0 = b*SEQ + n*64;
    int tid = threadIdx.x;
    int ty = tid >> 4, tx = tid & 15;

    float eqn = g_eta[  0 + b*16 + h];
    float ekn = g_eta[ 64 + b*16 + h];
    float eqp = g_eta[128 + b*16 + h];
    float ekp = g_eta[192 + b*16 + h];

    float c_pe[4][4], c_np[4][4];
#pragma unroll
    for (int i = 0; i < 4; i++)
#pragma unroll
        for (int j = 0; j < 4; j++) { c_pe[i][j] = 0.f; c_np[i][j] = 0.f; }

    for (int idx = tid; idx < 4096; idx += 256) {
        int q = idx >> 6, d = idx & 63;
        sA[d*65 + q] = g_q[(size_t)(m0+q)*QW + h*192 + DN + d];
        sB[d*65 + q] = g_kpe[(size_t)(m0+q)*DRD + d];
    }
    __syncthreads();
#pragma unroll 4
    for (int k = 0; k < 64; k++) {
        float a[4], bb[4];
#pragma unroll
        for (int i = 0; i < 4; i++) a[i]  = sA[k*65 + ty*4 + i];
#pragma unroll
        for (int j = 0; j < 4; j++) bb[j] = sB[k*65 + tx*4 + j];
#pragma unroll
        for (int i = 0; i < 4; i++)
#pragma unroll
            for (int j = 0; j < 4; j++)
                c_pe[i][j] = fmaf(a[i], bb[j], c_pe[i][j]);
    }
    __syncthreads();

    for (int ch = 0; ch < 2; ch++) {
        for (int idx = tid; idx < 4096; idx += 256) {
            int q = idx >> 6, d = idx & 63;
            sA[d*65 + q] = g_q  [(size_t)(m0+q)*QW   + h*192 + ch*64 + d];
            sB[d*65 + q] = g_kvb[(size_t)(m0+q)*KVBW + h*256 + ch*64 + d];
        }
        __syncthreads();
#pragma unroll 4
        for (int k = 0; k < 64; k++) {
            float a[4], bb[4];
#pragma unroll
            for (int i = 0; i < 4; i++) a[i]  = sA[k*65 + ty*4 + i];
#pragma unroll
            for (int j = 0; j < 4; j++) bb[j] = sB[k*65 + tx*4 + j];
#pragma unroll
            for (int i = 0; i < 4; i++)
#pragma unroll
                for (int j = 0; j < 4; j++)
                    c_np[i][j] = fmaf(a[i], bb[j], c_np[i][j]);
        }
        __syncthreads();
    }

    float fn = eqn * ekn * SCALE_F;
    float fp = eqp * ekp * SCALE_F;
#pragma unroll
    for (int i = 0; i < 4; i++)
#pragma unroll
        for (int j = 0; j < 4; j++) {
            int q = ty*4 + i, kk = tx*4 + j;
            float v = c_np[i][j]*fn + c_pe[i][j]*fp;
            if (kk > q) v = -3.402823466e38f;
            sA[q*65 + kk] = v;
        }
    __syncthreads();

    {
        int w = tid >> 5, lane = tid & 31;
        for (int r = w; r < 64; r += 8) {
            float x0 = sA[r*65 + lane];
            float x1 = sA[r*65 + lane + 32];
            float mx = fmaxf(x0, x1);
#pragma unroll
            for (int o = 16; o > 0; o >>= 1)
                mx = fmaxf(mx, __shfl_xor_sync(0xffffffffu, mx, o));
            float e0 = expf(x0 - mx);
            float e1 = expf(x1 - mx);
            float sm = e0 + e1;
#pragma unroll
            for (int o = 16; o > 0; o >>= 1)
                sm += __shfl_xor_sync(0xffffffffu, sm, o);
            float inv = 1.0f / sm;
            sA[r*65 + lane]      = e0 * inv;
            sA[r*65 + lane + 32] = e1 * inv;
        }
    }
    __syncthreads();

    for (int ch = 0; ch < 2; ch++) {
        for (int idx = tid; idx < 4096; idx += 256) {
            int kk = idx >> 6, d = idx & 63;
            sB[kk*65 + d] = g_kvb[(size_t)(m0+kk)*KVBW + h*256 + DN + ch*64 + d];
        }
        __syncthreads();
        float o[4][4];
#pragma unroll
        for (int i = 0; i < 4; i++)
#pragma unroll
            for (int j = 0; j < 4; j++) o[i][j] = 0.f;
#pragma unroll 4
        for (int k = 0; k < 64; k++) {
            float a[4], bb[4];
#pragma unroll
            for (int i = 0; i < 4; i++) a[i]  = sA[(ty*4 + i)*65 + k];
#pragma unroll
            for (int j = 0; j < 4; j++) bb[j] = sB[k*65 + tx*4 + j];
#pragma unroll
            for (int i = 0; i < 4; i++)
#pragma unroll
                for (int j = 0; j < 4; j++)
                    o[i][j] = fmaf(a[i], bb[j], o[i][j]);
        }
#pragma unroll
        for (int i = 0; i < 4; i++) {
            int m = m0 + ty*4 + i;
            int kk0 = h*DVD + ch*64 + tx*4;
#pragma unroll
            for (int j = 0; j < 4; j++)
                g_attnpk[a_pk_idx(m, kk0 + j, 256)] = f2tff(o[i][j]);
        }
        __syncthreads();
    }
}

// ---------------- launch ----------------
extern "C" void kernel_launch(void* const* d_in, const int* in_sizes, int n_in,
                              void* d_out, int out_size)
{
    const float* x     = (const float*)d_in[0];
    const float* fc    = (const float*)d_in[1];
    const float* wq_a  = (const float*)d_in[2];
    const float* wq_b  = (const float*)d_in[3];
    const float* wkv_a = (const float*)d_in[4];
    const float* wkv_b = (const float*)d_in[5];
    const float* wo    = (const float*)d_in[6];
    float* out = (float*)d_out;

    float *q, *kvb, *kperaw;
    float *xpk, *qlatpk, *kvapk, *attnpk;
    float *wqapk, *wqbpk, *wkapk, *wkbpk, *wopk;
    cudaGetSymbolAddress((void**)&q,      g_q);
    cudaGetSymbolAddress((void**)&kvb,    g_kvb);
    cudaGetSymbolAddress((void**)&kperaw, g_kperaw);
    cudaGetSymbolAddress((void**)&xpk,    g_xpk);
    cudaGetSymbolAddress((void**)&qlatpk, g_qlatpk);
    cudaGetSymbolAddress((void**)&kvapk,  g_kvapk);
    cudaGetSymbolAddress((void**)&attnpk, g_attnpk);
    cudaGetSymbolAddress((void**)&wqapk,  g_wqapk);
    cudaGetSymbolAddress((void**)&wqbpk,  g_wqbpk);
    cudaGetSymbolAddress((void**)&wkapk,  g_wkapk);
    cudaGetSymbolAddress((void**)&wkbpk,  g_wkbpk);
    cudaGetSymbolAddress((void**)&wopk,   g_wopk);

    cudaFuncSetAttribute(gemm_pk<0>, cudaFuncAttributeMaxDynamicSharedMemorySize, GEMM_SMEM);
    cudaFuncSetAttribute(gemm_pk<1>, cudaFuncAttributeMaxDynamicSharedMemorySize, GEMM_SMEM);
    cudaFuncSetAttribute(gemm_pk<2>, cudaFuncAttributeMaxDynamicSharedMemorySize, GEMM_SMEM);
    cudaFuncSetAttribute(gemm_pk<3>, cudaFuncAttributeMaxDynamicSharedMemorySize, GEMM_SMEM);
    cudaFuncSetAttribute(gemm_pk<4>, cudaFuncAttributeMaxDynamicSharedMemorySize, GEMM_SMEM);

    // packs
    pack_a_k<<<(MROWS*DMODEL)/256, 256>>>(x, xpk, DMODEL/8, DMODEL, MROWS*DMODEL);
    pack_b_k<<<(QLAT*DMODEL)/256, 256>>>(wq_a, wqapk, DMODEL/8, DMODEL, QLAT, QLAT*DMODEL);
    pack_b_k<<<(QW*QLAT)/256, 256>>>(wq_b, wqbpk, QLAT/8, QLAT, QW, QW*QLAT);
    pack_b_k<<<(KVAP*DMODEL)/256, 256>>>(wkv_a, wkapk, DMODEL/8, DMODEL, KVAW, KVAP*DMODEL);
    pack_b_k<<<(KVBW*KVLAT)/256, 256>>>(wkv_b, wkbpk, KVLAT/8, KVLAT, KVBW, KVBW*KVLAT);
    eta_init_k<<<1, 256>>>();

    // q_lat = x @ wq_a^T  [16384,512] K=2048 -> packed
    gemm_pk<1><<<dim3(4, 64), 256, GEMM_SMEM>>>(xpk, wqapk, qlatpk, nullptr, QLAT, DMODEL, nullptr);
    // q = q_lat @ wq_b^T  [16384,3072] K=512 -> row-major + silu/rope + eta(0,2)
    gemm_pk<2><<<dim3(24, 64), 256, GEMM_SMEM>>>(qlatpk, wqbpk, q, nullptr, QW, QLAT, fc);
    // kv_a = x @ wkv_a^T  [16384,640] K=2048 -> packed kv_c + raw k_pe
    gemm_pk<3><<<dim3(5, 64), 256, GEMM_SMEM>>>(xpk, wkapk, kvapk, kperaw, KVAP, DMODEL, nullptr);
    // kvb = kv_c @ wkv_b^T  [16384,4096] K=512 -> row-major + silu + eta(1)
    gemm_pk<4><<<dim3(32, 64), 256, GEMM_SMEM>>>(kvapk, wkbpk, kvb, nullptr, KVBW, KVLAT, nullptr);

    rope_silu_kpe_k<<<(MROWS*32)/256, 256>>>(fc);
    eta_fin_k<<<1, 256>>>();

    attn_kernel<<<dim3(BQ*64, NH), 256>>>();

    pack_b_k<<<(DMODEL*OW)/256, 256>>>(wo, wopk, OW/8, OW, DMODEL, DMODEL*OW);
    // out = attn_out @ wo^T  [16384,2048] K=2048
    gemm_pk<0><<<dim3(16, 64), 256, GEMM_SMEM>>>(attnpk, wopk, out, nullptr, DMODEL, OW, nullptr);
}

// round 10
// speedup vs baseline: 1.4430x; 1.4430x over previous
#include <cuda_runtime.h>
#include <cuda_bf16.h>
#include <math.h>
#include <float.h>
#include <stdint.h>

// Problem constants
#define BQ      4
#define SEQ     4096
#define DMODEL  2048
#define NH      16
#define DN      128
#define DRD     64
#define DVD     128
#define QLAT    512
#define KVLAT   512
#define MROWS   (BQ*SEQ)          // 16384
#define QW      (NH*(DN+DRD))     // 3072
#define KVAW    (KVLAT+DRD)       // 576
#define KVAP    640               // padded N for wkv_a pack
#define KVBW    (NH*(DN+DVD))     // 4096
#define OW      (NH*DVD)          // 2048
#define SCALE_F 0.07216878364870323f

// ---------------- scratch ----------------
__device__ float g_q   [MROWS*QW];
__device__ float g_kvb [MROWS*KVBW];
__device__ float g_kpe [MROWS*DRD];
__device__ float g_kperaw[MROWS*DRD];
__device__ unsigned int g_eta_enc[256];
__device__ float g_eta[256];
// fragment-packed operands (tf32-rounded)
__device__ float g_xpk   [MROWS*DMODEL];
__device__ float g_qlatpk[MROWS*QLAT];
__device__ float g_kvapk [MROWS*KVLAT];
__device__ float g_attnpk[MROWS*OW];
__device__ float g_wqapk [QLAT*DMODEL];
__device__ float g_wqbpk [QW*QLAT];
__device__ float g_wkapk [KVAP*DMODEL];
__device__ float g_wkbpk [KVBW*KVLAT];
__device__ float g_wopk  [DMODEL*OW];

// ---------------- helpers ----------------
__device__ __forceinline__ float silu_f(float x) { return x / (1.0f + expf(-x)); }

__device__ __forceinline__ unsigned encf(float f) {
    unsigned u = __float_as_uint(f);
    return (u & 0x80000000u) ? ~u : (u | 0x80000000u);
}
__device__ __forceinline__ float decf(unsigned u) {
    return (u & 0x80000000u) ? __uint_as_float(u ^ 0x80000000u) : __uint_as_float(~u);
}
__device__ __forceinline__ uint32_t smem_u32(const void* p) {
    uint32_t a;
    asm("{ .reg .u64 t; cvta.to.shared.u64 t, %1; cvt.u32.u64 %0, t; }" : "=r"(a) : "l"(p));
    return a;
}
__device__ __forceinline__ void cpasync16(uint32_t dst, const void* src) {
    asm volatile("cp.async.cg.shared.global [%0], [%1], 16;" :: "r"(dst), "l"(src));
}
__device__ __forceinline__ void cp_commit() { asm volatile("cp.async.commit_group;" ::: "memory"); }
__device__ __forceinline__ void cp_wait1()  { asm volatile("cp.async.wait_group 1;"  ::: "memory"); }

__device__ __forceinline__ uint32_t f2tf(float f) {
    uint32_t r;
    asm("cvt.rna.tf32.f32 %0, %1;" : "=r"(r) : "f"(f));
    return r;
}
__device__ __forceinline__ float f2tff(float f) { return __uint_as_float(f2tf(f)); }

__device__ __forceinline__ void mma8(float* d, const uint32_t* a, const uint32_t* b) {
    asm volatile("mma.sync.aligned.m16n8k8.row.col.f32.tf32.tf32.f32 "
        "{%0,%1,%2,%3},{%4,%5,%6,%7},{%8,%9},{%0,%1,%2,%3};"
        : "+f"(d[0]), "+f"(d[1]), "+f"(d[2]), "+f"(d[3])
        : "r"(a[0]), "r"(a[1]), "r"(a[2]), "r"(a[3]), "r"(b[0]), "r"(b[1]));
}

// packed-A element index: m,k -> offset (Kt = K/8 tiles)
__device__ __forceinline__ size_t a_pk_idx(int m, int k, int Kt) {
    int tm = m >> 4, rr = m & 15, lr = rr & 7, hi = rr >> 3;
    int tk = k >> 3, k7 = k & 7, qk = (k7 >> 2) << 1, lc = k7 & 3;
    return ((size_t)tm * Kt + tk) * 128 + (lr * 4 + lc) * 4 + qk + hi;
}

// ---------------- pack kernels (round to tf32) ----------------
__global__ void pack_a_k(const float* __restrict__ src, float* __restrict__ dst, int Kt, int ld, int n) {
    int o = blockIdx.x * blockDim.x + threadIdx.x;
    if (o >= n) return;
    int tile = o >> 7, l4q = o & 127, l = l4q >> 2, q = l4q & 3;
    int tm = tile / Kt, tk = tile % Kt;
    int r = tm * 16 + (q & 1) * 8 + (l >> 2);
    int k = tk * 8 + (q >> 1) * 4 + (l & 3);
    dst[o] = f2tff(src[(size_t)r * ld + k]);
}

__global__ void pack_b_k(const float* __restrict__ src, float* __restrict__ dst, int Kt, int ld, int N, int n) {
    int o = blockIdx.x * blockDim.x + threadIdx.x;
    if (o >= n) return;
    int tile = o >> 6, lq = o & 63, l = lq >> 1, q = lq & 1;
    int tn = tile / Kt, tk = tile % Kt;
    int nr = tn * 8 + (l >> 2);
    int k = tk * 8 + q * 4 + (l & 3);
    dst[o] = (nr < N) ? f2tff(src[(size_t)nr * ld + k]) : 0.0f;
}

// ---------------- packed tf32 GEMM: C[M,N] = A[M,K] @ B[N,K]^T ----------------
// BM=256, BN=128, BK=32, 512 threads (16 warps, 64x32 each), 3 stages, 1 CTA/SM.
// Fragment loads double-buffered in registers (ks+1 prefetched during ks MMAs).
// EPI: 0=plain  1=packed-A out(Kt=64)  2=Q silu/rope + eta  3=kva packed + kperaw  4=kvb silu + eta
#define STAGE_B 49152
#define GEMM_SMEM (3*STAGE_B)     // 144 KB

template<int EPI>
__global__ void __launch_bounds__(512, 1)
gemm_pk(const float* __restrict__ A, const float* __restrict__ B, float* __restrict__ C,
        float* __restrict__ C2, int N, int K, const float* __restrict__ fc)
{
    extern __shared__ float sm[];
    uint32_t sb = smem_u32(sm);
    int Kt = K >> 3;

    int tid  = threadIdx.x;
    int bm   = blockIdx.y * 256;
    int bn   = blockIdx.x * 128;
    int wid  = tid >> 5, lane = tid & 31;
    int wm   = (wid >> 2) * 64;
    int wn   = (wid & 3) * 32;
    int lr   = lane >> 2, lc = lane & 3;

    float acc[4][4][4];
#pragma unroll
    for (int t = 0; t < 4; t++)
#pragma unroll
        for (int j = 0; j < 4; j++)
#pragma unroll
            for (int v = 0; v < 4; v++) acc[t][j][v] = 0.f;

    auto loadStage = [&](int s, int ko) {
        uint32_t abase = sb + s * STAGE_B;
        uint32_t bbase = abase + 32768;
        int kt0 = ko >> 3;
#pragma unroll
        for (int j = 0; j < 4; j++) {
            int idx = j * 512 + tid;
            int tm = idx >> 7, u = idx & 127;
            const float* src = A + ((size_t)(bm / 16 + tm) * Kt + kt0) * 128 + u * 4;
            cpasync16(abase + tm * 2048 + u * 16, src);
        }
#pragma unroll
        for (int j = 0; j < 2; j++) {
            int idx = j * 512 + tid;
            int tn = idx >> 6, u = idx & 63;
            const float* src = B + ((size_t)(bn / 8 + tn) * Kt + kt0) * 64 + u * 4;
            cpasync16(bbase + tn * 1024 + u * 16, src);
        }
    };

    int nk = K / 32;
    loadStage(0, 0);  cp_commit();
    loadStage(1, 32); cp_commit();

    uint32_t af[2][4][4], bf[2][4][2];

    auto loadFrag = [&](const float* as, const float* bs, int ks, int buf) {
#pragma unroll
        for (int t = 0; t < 4; t++) {
            float4 v = *(const float4*)(as + ((wm >> 4) + t) * 512 + ks * 128 + lane * 4);
            af[buf][t][0] = __float_as_uint(v.x); af[buf][t][1] = __float_as_uint(v.y);
            af[buf][t][2] = __float_as_uint(v.z); af[buf][t][3] = __float_as_uint(v.w);
        }
#pragma unroll
        for (int j = 0; j < 4; j++) {
            float2 v = *(const float2*)(bs + ((wn >> 3) + j) * 256 + ks * 64 + lane * 2);
            bf[buf][j][0] = __float_as_uint(v.x); bf[buf][j][1] = __float_as_uint(v.y);
        }
    };

    for (int i = 0; i < nk; i++) {
        int s = i % 3;
        cp_wait1();
        __syncthreads();
        if (i + 2 < nk) loadStage((i + 2) % 3, (i + 2) * 32);
        cp_commit();

        const float* as = sm + s * (STAGE_B/4);
        const float* bs = as + 8192;
        loadFrag(as, bs, 0, 0);
#pragma unroll
        for (int ks = 0; ks < 4; ks++) {
            int cur = ks & 1;
            if (ks < 3) loadFrag(as, bs, ks + 1, cur ^ 1);
#pragma unroll
            for (int t = 0; t < 4; t++)
#pragma unroll
                for (int j = 0; j < 4; j++)
                    mma8(acc[t][j], af[cur][t], bf[cur][j]);
        }
    }

    // epilogue (+ optional fused eta max)
    float mnope = -FLT_MAX, mpe = -FLT_MAX;
#pragma unroll
    for (int t = 0; t < 4; t++) {
        int row0 = bm + wm + t * 16 + lr;
#pragma unroll
        for (int j = 0; j < 4; j++) {
            int col = bn + wn + j * 8 + lc * 2;
            float v0 = acc[t][j][0], v1 = acc[t][j][1], v2 = acc[t][j][2], v3 = acc[t][j][3];
            if (EPI == 0) {
                *(float2*)&C[(size_t)row0 * N + col]       = make_float2(v0, v1);
                *(float2*)&C[(size_t)(row0 + 8) * N + col] = make_float2(v2, v3);
            } else if (EPI == 1) {
                int tm = (bm + wm + t * 16) >> 4;
                int tk = col >> 3;
                int lp = lr * 4 + ((col & 7) & 3);
                int qk = (col & 4) >> 1;
                size_t base = ((size_t)tm * 64 + tk) * 128;
                *(float2*)&C[base + lp * 4 + qk]       = make_float2(f2tff(v0), f2tff(v2));
                *(float2*)&C[base + (lp + 1) * 4 + qk] = make_float2(f2tff(v1), f2tff(v3));
            } else if (EPI == 2) {
                int d = col % 192;
                if (d < DN) {
                    v0 = silu_f(v0); v1 = silu_f(v1); v2 = silu_f(v2); v3 = silu_f(v3);
                    mnope = fmaxf(mnope, fmaxf(fmaxf(v0, v1), fmaxf(v2, v3)));
                } else {
                    int p = (d - DN) >> 1;
                    int s0 = row0 & (SEQ - 1), s1 = (row0 + 8) & (SEQ - 1);
                    float c0 = fc[s0*64 + p*2], n0 = fc[s0*64 + p*2 + 1];
                    float c1 = fc[s1*64 + p*2], n1 = fc[s1*64 + p*2 + 1];
                    float r0 = v0*c0 - v1*n0, i0 = v0*n0 + v1*c0;
                    float r1 = v2*c1 - v3*n1, i1 = v2*n1 + v3*c1;
                    v0 = silu_f(r0); v1 = silu_f(i0); v2 = silu_f(r1); v3 = silu_f(i1);
                    mpe = fmaxf(mpe, fmaxf(fmaxf(v0, v1), fmaxf(v2, v3)));
                }
                *(float2*)&C[(size_t)row0 * N + col]       = make_float2(v0, v1);
                *(float2*)&C[(size_t)(row0 + 8) * N + col] = make_float2(v2, v3);
            } else if (EPI == 3) {
                if (col < KVLAT) {
                    int tm = (bm + wm + t * 16) >> 4;
                    int tk = col >> 3;
                    int lp = lr * 4 + ((col & 7) & 3);
                    int qk = (col & 4) >> 1;
                    size_t base = ((size_t)tm * 64 + tk) * 128;
                    *(float2*)&C[base + lp * 4 + qk]       = make_float2(f2tff(v0), f2tff(v2));
                    *(float2*)&C[base + (lp + 1) * 4 + qk] = make_float2(f2tff(v1), f2tff(v3));
                } else if (col < KVAW) {
                    *(float2*)&C2[(size_t)row0 * DRD + col - KVLAT]       = make_float2(v0, v1);
                    *(float2*)&C2[(size_t)(row0 + 8) * DRD + col - KVLAT] = make_float2(v2, v3);
                }
            } else if (EPI == 4) {
                int d = col % 256;
                if (d < DN) {
                    v0 = silu_f(v0); v1 = silu_f(v1); v2 = silu_f(v2); v3 = silu_f(v3);
                    mnope = fmaxf(mnope, fmaxf(fmaxf(v0, v1), fmaxf(v2, v3)));
                }
                *(float2*)&C[(size_t)row0 * N + col]       = make_float2(v0, v1);
                *(float2*)&C[(size_t)(row0 + 8) * N + col] = make_float2(v2, v3);
            }
        }
    }

    if (EPI == 2 || EPI == 4) {
        // CTA covers rows [bm, bm+256) = exactly eta group bm/256
        __syncthreads();
        sm[tid] = mnope;
        if (EPI == 2) sm[512 + tid] = mpe;
        __syncthreads();
        for (int st = 256; st > 0; st >>= 1) {
            if (tid < st) {
                sm[tid] = fmaxf(sm[tid], sm[tid + st]);
                if (EPI == 2) sm[512 + tid] = fmaxf(sm[512 + tid], sm[512 + tid + st]);
            }
            __syncthreads();
        }
        if (tid == 0) {
            int grp = bm >> 8;
            atomicMax(&g_eta_enc[(EPI == 2 ? 0 : 1) * 64 + grp], encf(sm[0]));
            if (EPI == 2) atomicMax(&g_eta_enc[2 * 64 + grp], encf(sm[512]));
        }
    }
}

// ---------------- rope+silu for k_pe + fused eta(t3) ----------------
__global__ void rope_silu_kpe_k(const float* __restrict__ fc) {
    __shared__ float red[256];
    int i = blockIdx.x * blockDim.x + threadIdx.x;
    int m = i >> 5;
    int p = i & 31;
    int s = m & (SEQ - 1);
    float c = fc[s*64 + p*2 + 0];
    float sn = fc[s*64 + p*2 + 1];
    float xr = g_kperaw[(size_t)m*DRD + 2*p];
    float xi = g_kperaw[(size_t)m*DRD + 2*p + 1];
    float y0 = silu_f(xr*c - xi*sn);
    float y1 = silu_f(xr*sn + xi*c);
    g_kpe[(size_t)m*DRD + 2*p]     = y0;
    g_kpe[(size_t)m*DRD + 2*p + 1] = y1;
    red[threadIdx.x] = fmaxf(y0, y1);
    __syncthreads();
    for (int st = 128; st > 0; st >>= 1) {
        if (threadIdx.x < st) red[threadIdx.x] = fmaxf(red[threadIdx.x], red[threadIdx.x + st]);
        __syncthreads();
    }
    if (threadIdx.x == 0) {
        int grp = blockIdx.x >> 5;      // 8 rows per block, 256 rows per group
        atomicMax(&g_eta_enc[3*64 + grp], encf(red[0]));
    }
}

// ---------------- eta ----------------
__global__ void eta_init_k() {
    if (threadIdx.x < 256) g_eta_enc[threadIdx.x] = 0u;
}

__global__ void eta_fin_k() {
    int i = threadIdx.x;
    if (i < 256) {
        float m = decf(g_eta_enc[i]);
        if (m == 0.0f) m = 1e-6f;
        g_eta[i] = fminf(10.0f / m, 1.0f);
    }
}

// ---------------- block attention (output packed for GEMM5 A) ----------------
__global__ void __launch_bounds__(256) attn_kernel() {
    __shared__ float sA[64*65];
    __shared__ float sB[64*65];
    int bnb = blockIdx.x;
    int h   = blockIdx.y;
    int b = bnb >> 6, n = bnb & 63;
    int m0 = b*SEQ + n*64;
    int tid = threadIdx.x;
    int ty = tid >> 4, tx = tid & 15;

    float eqn = g_eta[  0 + b*16 + h];
    float ekn = g_eta[ 64 + b*16 + h];
    float eqp = g_eta[128 + b*16 + h];
    float ekp = g_eta[192 + b*16 + h];

    float c_pe[4][4], c_np[4][4];
#pragma unroll
    for (int i = 0; i < 4; i++)
#pragma unroll
        for (int j = 0; j < 4; j++) { c_pe[i][j] = 0.f; c_np[i][j] = 0.f; }

    for (int idx = tid; idx < 4096; idx += 256) {
        int q = idx >> 6, d = idx & 63;
        sA[d*65 + q] = g_q[(size_t)(m0+q)*QW + h*192 + DN + d];
        sB[d*65 + q] = g_kpe[(size_t)(m0+q)*DRD + d];
    }
    __syncthreads();
#pragma unroll 4
    for (int k = 0; k < 64; k++) {
        float a[4], bb[4];
#pragma unroll
        for (int i = 0; i < 4; i++) a[i]  = sA[k*65 + ty*4 + i];
#pragma unroll
        for (int j = 0; j < 4; j++) bb[j] = sB[k*65 + tx*4 + j];
#pragma unroll
        for (int i = 0; i < 4; i++)
#pragma unroll
            for (int j = 0; j < 4; j++)
                c_pe[i][j] = fmaf(a[i], bb[j], c_pe[i][j]);
    }
    __syncthreads();

    for (int ch = 0; ch < 2; ch++) {
        for (int idx = tid; idx < 4096; idx += 256) {
            int q = idx >> 6, d = idx & 63;
            sA[d*65 + q] = g_q  [(size_t)(m0+q)*QW   + h*192 + ch*64 + d];
            sB[d*65 + q] = g_kvb[(size_t)(m0+q)*KVBW + h*256 + ch*64 + d];
        }
        __syncthreads();
#pragma unroll 4
        for (int k = 0; k < 64; k++) {
            float a[4], bb[4];
#pragma unroll
            for (int i = 0; i < 4; i++) a[i]  = sA[k*65 + ty*4 + i];
#pragma unroll
            for (int j = 0; j < 4; j++) bb[j] = sB[k*65 + tx*4 + j];
#pragma unroll
            for (int i = 0; i < 4; i++)
#pragma unroll
                for (int j = 0; j < 4; j++)
                    c_np[i][j] = fmaf(a[i], bb[j], c_np[i][j]);
        }
        __syncthreads();
    }

    float fn = eqn * ekn * SCALE_F;
    float fp = eqp * ekp * SCALE_F;
#pragma unroll
    for (int i = 0; i < 4; i++)
#pragma unroll
        for (int j = 0; j < 4; j++) {
            int q = ty*4 + i, kk = tx*4 + j;
            float v = c_np[i][j]*fn + c_pe[i][j]*fp;
            if (kk > q) v = -3.402823466e38f;
            sA[q*65 + kk] = v;
        }
    __syncthreads();

    {
        int w = tid >> 5, lane = tid & 31;
        for (int r = w; r < 64; r += 8) {
            float x0 = sA[r*65 + lane];
            float x1 = sA[r*65 + lane + 32];
            float mx = fmaxf(x0, x1);
#pragma unroll
            for (int o = 16; o > 0; o >>= 1)
                mx = fmaxf(mx, __shfl_xor_sync(0xffffffffu, mx, o));
            float e0 = expf(x0 - mx);
            float e1 = expf(x1 - mx);
            float sm = e0 + e1;
#pragma unroll
            for (int o = 16; o > 0; o >>= 1)
                sm += __shfl_xor_sync(0xffffffffu, sm, o);
            float inv = 1.0f / sm;
            sA[r*65 + lane]      = e0 * inv;
            sA[r*65 + lane + 32] = e1 * inv;
        }
    }
    __syncthreads();

    for (int ch = 0; ch < 2; ch++) {
        for (int idx = tid; idx < 4096; idx += 256) {
            int kk = idx >> 6, d = idx & 63;
            sB[kk*65 + d] = g_kvb[(size_t)(m0+kk)*KVBW + h*256 + DN + ch*64 + d];
        }
        __syncthreads();
        float o[4][4];
#pragma unroll
        for (int i = 0; i < 4; i++)
#pragma unroll
            for (int j = 0; j < 4; j++) o[i][j] = 0.f;
#pragma unroll 4
        for (int k = 0; k < 64; k++) {
            float a[4], bb[4];
#pragma unroll
            for (int i = 0; i < 4; i++) a[i]  = sA[(ty*4 + i)*65 + k];
#pragma unroll
            for (int j = 0; j < 4; j++) bb[j] = sB[k*65 + tx*4 + j];
#pragma unroll
            for (int i = 0; i < 4; i++)
#pragma unroll
                for (int j = 0; j < 4; j++)
                    o[i][j] = fmaf(a[i], bb[j], o[i][j]);
        }
#pragma unroll
        for (int i = 0; i < 4; i++) {
            int m = m0 + ty*4 + i;
            int kk0 = h*DVD + ch*64 + tx*4;
#pragma unroll
            for (int j = 0; j < 4; j++)
                g_attnpk[a_pk_idx(m, kk0 + j, 256)] = f2tff(o[i][j]);
        }
        __syncthreads();
    }
}

// ---------------- launch ----------------
extern "C" void kernel_launch(void* const* d_in, const int* in_sizes, int n_in,
                              void* d_out, int out_size)
{
    const float* x     = (const float*)d_in[0];
    const float* fc    = (const float*)d_in[1];
    const float* wq_a  = (const float*)d_in[2];
    const float* wq_b  = (const float*)d_in[3];
    const float* wkv_a = (const float*)d_in[4];
    const float* wkv_b = (const float*)d_in[5];
    const float* wo    = (const float*)d_in[6];
    float* out = (float*)d_out;

    float *q, *kvb, *kperaw;
    float *xpk, *qlatpk, *kvapk, *attnpk;
    float *wqapk, *wqbpk, *wkapk, *wkbpk, *wopk;
    cudaGetSymbolAddress((void**)&q,      g_q);
    cudaGetSymbolAddress((void**)&kvb,    g_kvb);
    cudaGetSymbolAddress((void**)&kperaw, g_kperaw);
    cudaGetSymbolAddress((void**)&xpk,    g_xpk);
    cudaGetSymbolAddress((void**)&qlatpk, g_qlatpk);
    cudaGetSymbolAddress((void**)&kvapk,  g_kvapk);
    cudaGetSymbolAddress((void**)&attnpk, g_attnpk);
    cudaGetSymbolAddress((void**)&wqapk,  g_wqapk);
    cudaGetSymbolAddress((void**)&wqbpk,  g_wqbpk);
    cudaGetSymbolAddress((void**)&wkapk,  g_wkapk);
    cudaGetSymbolAddress((void**)&wkbpk,  g_wkbpk);
    cudaGetSymbolAddress((void**)&wopk,   g_wopk);

    cudaFuncSetAttribute(gemm_pk<0>, cudaFuncAttributeMaxDynamicSharedMemorySize, GEMM_SMEM);
    cudaFuncSetAttribute(gemm_pk<1>, cudaFuncAttributeMaxDynamicSharedMemorySize, GEMM_SMEM);
    cudaFuncSetAttribute(gemm_pk<2>, cudaFuncAttributeMaxDynamicSharedMemorySize, GEMM_SMEM);
    cudaFuncSetAttribute(gemm_pk<3>, cudaFuncAttributeMaxDynamicSharedMemorySize, GEMM_SMEM);
    cudaFuncSetAttribute(gemm_pk<4>, cudaFuncAttributeMaxDynamicSharedMemorySize, GEMM_SMEM);

    // packs
    pack_a_k<<<(MROWS*DMODEL)/256, 256>>>(x, xpk, DMODEL/8, DMODEL, MROWS*DMODEL);
    pack_b_k<<<(QLAT*DMODEL)/256, 256>>>(wq_a, wqapk, DMODEL/8, DMODEL, QLAT, QLAT*DMODEL);
    pack_b_k<<<(QW*QLAT)/256, 256>>>(wq_b, wqbpk, QLAT/8, QLAT, QW, QW*QLAT);
    pack_b_k<<<(KVAP*DMODEL)/256, 256>>>(wkv_a, wkapk, DMODEL/8, DMODEL, KVAW, KVAP*DMODEL);
    pack_b_k<<<(KVBW*KVLAT)/256, 256>>>(wkv_b, wkbpk, KVLAT/8, KVLAT, KVBW, KVBW*KVLAT);
    pack_b_k<<<(DMODEL*OW)/256, 256>>>(wo, wopk, OW/8, OW, DMODEL, DMODEL*OW);
    eta_init_k<<<1, 256>>>();

    // q_lat = x @ wq_a^T  [16384,512] K=2048 -> packed
    gemm_pk<1><<<dim3(4, 64), 512, GEMM_SMEM>>>(xpk, wqapk, qlatpk, nullptr, QLAT, DMODEL, nullptr);
    // q = q_lat @ wq_b^T  [16384,3072] K=512 -> row-major + silu/rope + eta(0,2)
    gemm_pk<2><<<dim3(24, 64), 512, GEMM_SMEM>>>(qlatpk, wqbpk, q, nullptr, QW, QLAT, fc);
    // kv_a = x @ wkv_a^T  [16384,640] K=2048 -> packed kv_c + raw k_pe
    gemm_pk<3><<<dim3(5, 64), 512, GEMM_SMEM>>>(xpk, wkapk, kvapk, kperaw, KVAP, DMODEL, nullptr);
    // kvb = kv_c @ wkv_b^T  [16384,4096] K=512 -> row-major + silu + eta(1)
    gemm_pk<4><<<dim3(32, 64), 512, GEMM_SMEM>>>(kvapk, wkbpk, kvb, nullptr, KVBW, KVLAT, nullptr);

    rope_silu_kpe_k<<<(MROWS*32)/256, 256>>>(fc);
    eta_fin_k<<<1, 256>>>();

    attn_kernel<<<dim3(BQ*64, NH), 256>>>();

    // out = attn_out @ wo^T  [16384,2048] K=2048
    gemm_pk<0><<<dim3(16, 64), 512, GEMM_SMEM>>>(attnpk, wopk, out, nullptr, DMODEL, OW, nullptr);
}

// round 12
// speedup vs baseline: 1.6261x; 1.1269x over previous
#include <cuda_runtime.h>
#include <cuda_bf16.h>
#include <math.h>
#include <float.h>
#include <stdint.h>

// Problem constants
#define BQ      4
#define SEQ     4096
#define DMODEL  2048
#define NH      16
#define DN      128
#define DRD     64
#define DVD     128
#define QLAT    512
#define KVLAT   512
#define MROWS   (BQ*SEQ)          // 16384
#define QW      (NH*(DN+DRD))     // 3072
#define KVAW    (KVLAT+DRD)       // 576
#define KVAP    640               // padded kva width
#define NCOMB   (QLAT+KVAP)       // 1152 combined GEMM1+3 width
#define KVBW    (NH*(DN+DVD))     // 4096
#define OW      (NH*DVD)          // 2048
#define SCALE_F 0.07216878364870323f

// ---------------- scratch ----------------
__device__ float g_q   [MROWS*QW];
__device__ float g_kvb [MROWS*KVBW];
__device__ float g_kpe [MROWS*DRD];
__device__ unsigned int g_eta_enc[256];
__device__ float g_eta[256];
// fragment-packed operands (tf32-rounded)
__device__ float g_xpk   [MROWS*DMODEL];
__device__ float g_qlatpk[MROWS*QLAT];
__device__ float g_kvapk [MROWS*KVLAT];
__device__ float g_attnpk[MROWS*OW];
__device__ float g_wqkapk[NCOMB*DMODEL];    // wq_a tiles then wkv_a tiles
__device__ float g_wqbpk [QW*QLAT];
__device__ float g_wkbpk [KVBW*KVLAT];
__device__ float g_wopk  [DMODEL*OW];

// ---------------- helpers ----------------
__device__ __forceinline__ float silu_f(float x) { return x / (1.0f + expf(-x)); }

__device__ __forceinline__ unsigned encf(float f) {
    unsigned u = __float_as_uint(f);
    return (u & 0x80000000u) ? ~u : (u | 0x80000000u);
}
__device__ __forceinline__ float decf(unsigned u) {
    return (u & 0x80000000u) ? __uint_as_float(u ^ 0x80000000u) : __uint_as_float(~u);
}
__device__ __forceinline__ uint32_t smem_u32(const void* p) {
    uint32_t a;
    asm("{ .reg .u64 t; cvta.to.shared.u64 t, %1; cvt.u32.u64 %0, t; }" : "=r"(a) : "l"(p));
    return a;
}
__device__ __forceinline__ void cpasync16(uint32_t dst, const void* src) {
    asm volatile("cp.async.cg.shared.global [%0], [%1], 16;" :: "r"(dst), "l"(src));
}
__device__ __forceinline__ void cp_commit() { asm volatile("cp.async.commit_group;" ::: "memory"); }
__device__ __forceinline__ void cp_wait1()  { asm volatile("cp.async.wait_group 1;"  ::: "memory"); }

__device__ __forceinline__ uint32_t f2tf(float f) {
    uint32_t r;
    asm("cvt.rna.tf32.f32 %0, %1;" : "=r"(r) : "f"(f));
    return r;
}
__device__ __forceinline__ float f2tff(float f) { return __uint_as_float(f2tf(f)); }

__device__ __forceinline__ void mma8(float* d, const uint32_t* a, const uint32_t* b) {
    asm volatile("mma.sync.aligned.m16n8k8.row.col.f32.tf32.tf32.f32 "
        "{%0,%1,%2,%3},{%4,%5,%6,%7},{%8,%9},{%0,%1,%2,%3};"
        : "+f"(d[0]), "+f"(d[1]), "+f"(d[2]), "+f"(d[3])
        : "r"(a[0]), "r"(a[1]), "r"(a[2]), "r"(a[3]), "r"(b[0]), "r"(b[1]));
}

// packed-A element index: m,k -> offset (Kt = K/8 tiles)
__device__ __forceinline__ size_t a_pk_idx(int m, int k, int Kt) {
    int tm = m >> 4, rr = m & 15, lr = rr & 7, hi = rr >> 3;
    int tk = k >> 3, k7 = k & 7, qk = (k7 >> 2) << 1, lc = k7 & 3;
    return ((size_t)tm * Kt + tk) * 128 + (lr * 4 + lc) * 4 + qk + hi;
}

// ---------------- pack kernels (round to tf32) ----------------
__global__ void pack_a_k(const float* __restrict__ src, float* __restrict__ dst, int Kt, int ld, int n) {
    int o = blockIdx.x * blockDim.x + threadIdx.x;
    if (o >= n) return;
    int tile = o >> 7, l4q = o & 127, l = l4q >> 2, q = l4q & 3;
    int tm = tile / Kt, tk = tile % Kt;
    int r = tm * 16 + (q & 1) * 8 + (l >> 2);
    int k = tk * 8 + (q >> 1) * 4 + (l & 3);
    dst[o] = f2tff(src[(size_t)r * ld + k]);
}

__global__ void pack_b_k(const float* __restrict__ src, float* __restrict__ dst, int Kt, int ld, int N, int n) {
    int o = blockIdx.x * blockDim.x + threadIdx.x;
    if (o >= n) return;
    int tile = o >> 6, lq = o & 63, l = lq >> 1, q = lq & 1;
    int tn = tile / Kt, tk = tile % Kt;
    int nr = tn * 8 + (l >> 2);
    int k = tk * 8 + q * 4 + (l & 3);
    dst[o] = (nr < N) ? f2tff(src[(size_t)nr * ld + k]) : 0.0f;
}

// ---------------- packed tf32 GEMM: C[M,N] = A[M,K] @ B[N,K]^T ----------------
// BM=256, BN=128, BK=32, 512 threads (16 warps, 64x32 each), 3 stages, 1 CTA/SM.
// EPI: 0=plain  2=Q silu/rope + eta  4=kvb silu + eta
//      5=combined GEMM1+3: cols[0,512) qlat packed, [512,1024) kva packed,
//        [1024,1088) kpe rope+silu+eta, [1088,1152) padding
#define STAGE_B 49152
#define GEMM_SMEM (3*STAGE_B)     // 144 KB

template<int EPI>
__global__ void __launch_bounds__(512, 1)
gemm_pk(const float* __restrict__ A, const float* __restrict__ B, float* __restrict__ C,
        int N, int K, const float* __restrict__ fc)
{
    extern __shared__ float sm[];
    uint32_t sb = smem_u32(sm);
    int Kt = K >> 3;

    int tid  = threadIdx.x;
    int bm   = blockIdx.y * 256;
    int bn   = blockIdx.x * 128;
    int wid  = tid >> 5, lane = tid & 31;
    int wm   = (wid >> 2) * 64;
    int wn   = (wid & 3) * 32;
    int lr   = lane >> 2, lc = lane & 3;

    float acc[4][4][4];
#pragma unroll
    for (int t = 0; t < 4; t++)
#pragma unroll
        for (int j = 0; j < 4; j++)
#pragma unroll
            for (int v = 0; v < 4; v++) acc[t][j][v] = 0.f;

    auto loadStage = [&](int s, int ko) {
        uint32_t abase = sb + s * STAGE_B;
        uint32_t bbase = abase + 32768;
        int kt0 = ko >> 3;
#pragma unroll
        for (int j = 0; j < 4; j++) {
            int idx = j * 512 + tid;
            int tm = idx >> 7, u = idx & 127;
            const float* src = A + ((size_t)(bm / 16 + tm) * Kt + kt0) * 128 + u * 4;
            cpasync16(abase + tm * 2048 + u * 16, src);
        }
#pragma unroll
        for (int j = 0; j < 2; j++) {
            int idx = j * 512 + tid;
            int tn = idx >> 6, u = idx & 63;
            const float* src = B + ((size_t)(bn / 8 + tn) * Kt + kt0) * 64 + u * 4;
            cpasync16(bbase + tn * 1024 + u * 16, src);
        }
    };

    int nk = K / 32;
    loadStage(0, 0);  cp_commit();
    loadStage(1, 32); cp_commit();

    for (int i = 0; i < nk; i++) {
        int s = i % 3;
        cp_wait1();
        __syncthreads();
        if (i + 2 < nk) loadStage((i + 2) % 3, (i + 2) * 32);
        cp_commit();

        const float* as = sm + s * (STAGE_B/4);
        const float* bs = as + 8192;
#pragma unroll
        for (int ks = 0; ks < 4; ks++) {
            uint32_t af[4][4], bf[4][2];
#pragma unroll
            for (int t = 0; t < 4; t++) {
                float4 v = *(const float4*)(as + ((wm >> 4) + t) * 512 + ks * 128 + lane * 4);
                af[t][0] = __float_as_uint(v.x); af[t][1] = __float_as_uint(v.y);
                af[t][2] = __float_as_uint(v.z); af[t][3] = __float_as_uint(v.w);
            }
#pragma unroll
            for (int j = 0; j < 4; j++) {
                float2 v = *(const float2*)(bs + ((wn >> 3) + j) * 256 + ks * 64 + lane * 2);
                bf[j][0] = __float_as_uint(v.x); bf[j][1] = __float_as_uint(v.y);
            }
#pragma unroll
            for (int t = 0; t < 4; t++)
#pragma unroll
                for (int j = 0; j < 4; j++)
                    mma8(acc[t][j], af[t], bf[j]);
        }
    }

    // epilogue (+ optional fused eta max)
    float mnope = -FLT_MAX, mpe = -FLT_MAX;
#pragma unroll
    for (int t = 0; t < 4; t++) {
        int row0 = bm + wm + t * 16 + lr;
#pragma unroll
        for (int j = 0; j < 4; j++) {
            int col = bn + wn + j * 8 + lc * 2;
            float v0 = acc[t][j][0], v1 = acc[t][j][1], v2 = acc[t][j][2], v3 = acc[t][j][3];
            if (EPI == 0) {
                *(float2*)&C[(size_t)row0 * N + col]       = make_float2(v0, v1);
                *(float2*)&C[(size_t)(row0 + 8) * N + col] = make_float2(v2, v3);
            } else if (EPI == 2) {
                int d = col % 192;
                if (d < DN) {
                    v0 = silu_f(v0); v1 = silu_f(v1); v2 = silu_f(v2); v3 = silu_f(v3);
                    mnope = fmaxf(mnope, fmaxf(fmaxf(v0, v1), fmaxf(v2, v3)));
                } else {
                    int p = (d - DN) >> 1;
                    int s0 = row0 & (SEQ - 1), s1 = (row0 + 8) & (SEQ - 1);
                    float c0 = fc[s0*64 + p*2], n0 = fc[s0*64 + p*2 + 1];
                    float c1 = fc[s1*64 + p*2], n1 = fc[s1*64 + p*2 + 1];
                    float r0 = v0*c0 - v1*n0, i0 = v0*n0 + v1*c0;
                    float r1 = v2*c1 - v3*n1, i1 = v2*n1 + v3*c1;
                    v0 = silu_f(r0); v1 = silu_f(i0); v2 = silu_f(r1); v3 = silu_f(i1);
                    mpe = fmaxf(mpe, fmaxf(fmaxf(v0, v1), fmaxf(v2, v3)));
                }
                *(float2*)&C[(size_t)row0 * N + col]       = make_float2(v0, v1);
                *(float2*)&C[(size_t)(row0 + 8) * N + col] = make_float2(v2, v3);
            } else if (EPI == 4) {
                int d = col % 256;
                if (d < DN) {
                    v0 = silu_f(v0); v1 = silu_f(v1); v2 = silu_f(v2); v3 = silu_f(v3);
                    mnope = fmaxf(mnope, fmaxf(fmaxf(v0, v1), fmaxf(v2, v3)));
                }
                *(float2*)&C[(size_t)row0 * N + col]       = make_float2(v0, v1);
                *(float2*)&C[(size_t)(row0 + 8) * N + col] = make_float2(v2, v3);
            } else if (EPI == 5) {
                int tm = (bm + wm + t * 16) >> 4;
                if (col < QLAT) {
                    // qlat packed out, Kt_out = 64
                    int tk = col >> 3;
                    int lp = lr * 4 + ((col & 7) & 3);
                    int qk = (col & 4) >> 1;
                    size_t base = ((size_t)tm * 64 + tk) * 128;
                    *(float2*)&g_qlatpk[base + lp * 4 + qk]       = make_float2(f2tff(v0), f2tff(v2));
                    *(float2*)&g_qlatpk[base + (lp + 1) * 4 + qk] = make_float2(f2tff(v1), f2tff(v3));
                } else {
                    int col2 = col - QLAT;
                    if (col2 < KVLAT) {
                        // kva packed out, Kt_out = 64
                        int tk = col2 >> 3;
                        int lp = lr * 4 + ((col2 & 7) & 3);
                        int qk = (col2 & 4) >> 1;
                        size_t base = ((size_t)tm * 64 + tk) * 128;
                        *(float2*)&g_kvapk[base + lp * 4 + qk]       = make_float2(f2tff(v0), f2tff(v2));
                        *(float2*)&g_kvapk[base + (lp + 1) * 4 + qk] = make_float2(f2tff(v1), f2tff(v3));
                    } else if (col2 < KVAW) {
                        // kpe: rope + silu + eta(t3)
                        int d = col2 - KVLAT;            // even
                        int p = d >> 1;
                        int s0 = row0 & (SEQ - 1), s1 = (row0 + 8) & (SEQ - 1);
                        float c0 = fc[s0*64 + p*2], n0 = fc[s0*64 + p*2 + 1];
                        float c1 = fc[s1*64 + p*2], n1 = fc[s1*64 + p*2 + 1];
                        float y00 = silu_f(v0*c0 - v1*n0);
                        float y01 = silu_f(v0*n0 + v1*c0);
                        float y10 = silu_f(v2*c1 - v3*n1);
                        float y11 = silu_f(v2*n1 + v3*c1);
                        *(float2*)&g_kpe[(size_t)row0 * DRD + d]       = make_float2(y00, y01);
                        *(float2*)&g_kpe[(size_t)(row0 + 8) * DRD + d] = make_float2(y10, y11);
                        mpe = fmaxf(mpe, fmaxf(fmaxf(y00, y01), fmaxf(y10, y11)));
                    }
                }
            }
        }
    }

    if (EPI == 2 || EPI == 4 || EPI == 5) {
        __syncthreads();
        sm[tid] = mnope;
        sm[512 + tid] = mpe;
        __syncthreads();
        for (int st = 256; st > 0; st >>= 1) {
            if (tid < st) {
                sm[tid] = fmaxf(sm[tid], sm[tid + st]);
                sm[512 + tid] = fmaxf(sm[512 + tid], sm[512 + tid + st]);
            }
            __syncthreads();
        }
        if (tid == 0) {
            int grp = bm >> 8;
            if (EPI == 2) {
                atomicMax(&g_eta_enc[grp], encf(sm[0]));
                atomicMax(&g_eta_enc[128 + grp], encf(sm[512]));
            } else if (EPI == 4) {
                atomicMax(&g_eta_enc[64 + grp], encf(sm[0]));
            } else if (EPI == 5) {
                if (blockIdx.x == 8)        // only the col-block containing kpe
                    atomicMax(&g_eta_enc[192 + grp], encf(sm[512]));
            }
        }
    }
}

// ---------------- eta ----------------
__global__ void eta_init_k() {
    if (threadIdx.x < 256) g_eta_enc[threadIdx.x] = 0u;
}

__global__ void eta_fin_k() {
    int i = threadIdx.x;
    if (i < 256) {
        float m = decf(g_eta_enc[i]);
        if (m == 0.0f) m = 1e-6f;
        g_eta[i] = fminf(10.0f / m, 1.0f);
    }
}

// ---------------- block attention (output packed for GEMM5 A) ----------------
__global__ void __launch_bounds__(256) attn_kernel() {
    __shared__ float sA[64*65];
    __shared__ float sB[64*65];
    int bnb = blockIdx.x;
    int h   = blockIdx.y;
    int b = bnb >> 6, n = bnb & 63;
    int m0 = b*SEQ + n*64;
    int tid = threadIdx.x;
    int ty = tid >> 4, tx = tid & 15;

    float eqn = g_eta[  0 + b*16 + h];
    float ekn = g_eta[ 64 + b*16 + h];
    float eqp = g_eta[128 + b*16 + h];
    float ekp = g_eta[192 + b*16 + h];

    float c_pe[4][4], c_np[4][4];
#pragma unroll
    for (int i = 0; i < 4; i++)
#pragma unroll
        for (int j = 0; j < 4; j++) { c_pe[i][j] = 0.f; c_np[i][j] = 0.f; }

    for (int idx = tid; idx < 4096; idx += 256) {
        int q = idx >> 6, d = idx & 63;
        sA[d*65 + q] = g_q[(size_t)(m0+q)*QW + h*192 + DN + d];
        sB[d*65 + q] = g_kpe[(size_t)(m0+q)*DRD + d];
    }
    __syncthreads();
#pragma unroll 4
    for (int k = 0; k < 64; k++) {
        float a[4], bb[4];
#pragma unroll
        for (int i = 0; i < 4; i++) a[i]  = sA[k*65 + ty*4 + i];
#pragma unroll
        for (int j = 0; j < 4; j++) bb[j] = sB[k*65 + tx*4 + j];
#pragma unroll
        for (int i = 0; i < 4; i++)
#pragma unroll
            for (int j = 0; j < 4; j++)
                c_pe[i][j] = fmaf(a[i], bb[j], c_pe[i][j]);
    }
    __syncthreads();

    for (int ch = 0; ch < 2; ch++) {
        for (int idx = tid; idx < 4096; idx += 256) {
            int q = idx >> 6, d = idx & 63;
            sA[d*65 + q] = g_q  [(size_t)(m0+q)*QW   + h*192 + ch*64 + d];
            sB[d*65 + q] = g_kvb[(size_t)(m0+q)*KVBW + h*256 + ch*64 + d];
        }
        __syncthreads();
#pragma unroll 4
        for (int k = 0; k < 64; k++) {
            float a[4], bb[4];
#pragma unroll
            for (int i = 0; i < 4; i++) a[i]  = sA[k*65 + ty*4 + i];
#pragma unroll
            for (int j = 0; j < 4; j++) bb[j] = sB[k*65 + tx*4 + j];
#pragma unroll
            for (int i = 0; i < 4; i++)
#pragma unroll
                for (int j = 0; j < 4; j++)
                    c_np[i][j] = fmaf(a[i], bb[j], c_np[i][j]);
        }
        __syncthreads();
    }

    float fn = eqn * ekn * SCALE_F;
    float fp = eqp * ekp * SCALE_F;
#pragma unroll
    for (int i = 0; i < 4; i++)
#pragma unroll
        for (int j = 0; j < 4; j++) {
            int q = ty*4 + i, kk = tx*4 + j;
            float v = c_np[i][j]*fn + c_pe[i][j]*fp;
            if (kk > q) v = -3.402823466e38f;
            sA[q*65 + kk] = v;
        }
    __syncthreads();

    {
        int w = tid >> 5, lane = tid & 31;
        for (int r = w; r < 64; r += 8) {
            float x0 = sA[r*65 + lane];
            float x1 = sA[r*65 + lane + 32];
            float mx = fmaxf(x0, x1);
#pragma unroll
            for (int o = 16; o > 0; o >>= 1)
                mx = fmaxf(mx, __shfl_xor_sync(0xffffffffu, mx, o));
            float e0 = expf(x0 - mx);
            float e1 = expf(x1 - mx);
            float sm = e0 + e1;
#pragma unroll
            for (int o = 16; o > 0; o >>= 1)
                sm += __shfl_xor_sync(0xffffffffu, sm, o);
            float inv = 1.0f / sm;
            sA[r*65 + lane]      = e0 * inv;
            sA[r*65 + lane + 32] = e1 * inv;
        }
    }
    __syncthreads();

    for (int ch = 0; ch < 2; ch++) {
        for (int idx = tid; idx < 4096; idx += 256) {
            int kk = idx >> 6, d = idx & 63;
            sB[kk*65 + d] = g_kvb[(size_t)(m0+kk)*KVBW + h*256 + DN + ch*64 + d];
        }
        __syncthreads();
        float o[4][4];
#pragma unroll
        for (int i = 0; i < 4; i++)
#pragma unroll
            for (int j = 0; j < 4; j++) o[i][j] = 0.f;
#pragma unroll 4
        for (int k = 0; k < 64; k++) {
            float a[4], bb[4];
#pragma unroll
            for (int i = 0; i < 4; i++) a[i]  = sA[(ty*4 + i)*65 + k];
#pragma unroll
            for (int j = 0; j < 4; j++) bb[j] = sB[k*65 + tx*4 + j];
#pragma unroll
            for (int i = 0; i < 4; i++)
#pragma unroll
                for (int j = 0; j < 4; j++)
                    o[i][j] = fmaf(a[i], bb[j], o[i][j]);
        }
#pragma unroll
        for (int i = 0; i < 4; i++) {
            int m = m0 + ty*4 + i;
            int kk0 = h*DVD + ch*64 + tx*4;
#pragma unroll
            for (int j = 0; j < 4; j++)
                g_attnpk[a_pk_idx(m, kk0 + j, 256)] = f2tff(o[i][j]);
        }
        __syncthreads();
    }
}

// ---------------- launch ----------------
extern "C" void kernel_launch(void* const* d_in, const int* in_sizes, int n_in,
                              void* d_out, int out_size)
{
    const float* x     = (const float*)d_in[0];
    const float* fc    = (const float*)d_in[1];
    const float* wq_a  = (const float*)d_in[2];
    const float* wq_b  = (const float*)d_in[3];
    const float* wkv_a = (const float*)d_in[4];
    const float* wkv_b = (const float*)d_in[5];
    const float* wo    = (const float*)d_in[6];
    float* out = (float*)d_out;

    float *q, *kvb;
    float *xpk, *qlatpk, *kvapk, *attnpk;
    float *wqkapk, *wqbpk, *wkbpk, *wopk;
    cudaGetSymbolAddress((void**)&q,      g_q);
    cudaGetSymbolAddress((void**)&kvb,    g_kvb);
    cudaGetSymbolAddress((void**)&xpk,    g_xpk);
    cudaGetSymbolAddress((void**)&qlatpk, g_qlatpk);
    cudaGetSymbolAddress((void**)&kvapk,  g_kvapk);
    cudaGetSymbolAddress((void**)&attnpk, g_attnpk);
    cudaGetSymbolAddress((void**)&wqkapk, g_wqkapk);
    cudaGetSymbolAddress((void**)&wqbpk,  g_wqbpk);
    cudaGetSymbolAddress((void**)&wkbpk,  g_wkbpk);
    cudaGetSymbolAddress((void**)&wopk,   g_wopk);

    cudaFuncSetAttribute(gemm_pk<0>, cudaFuncAttributeMaxDynamicSharedMemorySize, GEMM_SMEM);
    cudaFuncSetAttribute(gemm_pk<2>, cudaFuncAttributeMaxDynamicSharedMemorySize, GEMM_SMEM);
    cudaFuncSetAttribute(gemm_pk<4>, cudaFuncAttributeMaxDynamicSharedMemorySize, GEMM_SMEM);
    cudaFuncSetAttribute(gemm_pk<5>, cudaFuncAttributeMaxDynamicSharedMemorySize, GEMM_SMEM);

    // packs: wq_a tiles at offset 0, wkv_a tiles after (combined B for GEMM1+3)
    pack_a_k<<<(MROWS*DMODEL)/256, 256>>>(x, xpk, DMODEL/8, DMODEL, MROWS*DMODEL);
    pack_b_k<<<(QLAT*DMODEL)/256, 256>>>(wq_a, wqkapk, DMODEL/8, DMODEL, QLAT, QLAT*DMODEL);
    pack_b_k<<<(KVAP*DMODEL)/256, 256>>>(wkv_a, wqkapk + (size_t)QLAT*DMODEL, DMODEL/8, DMODEL, KVAW, KVAP*DMODEL);
    pack_b_k<<<(QW*QLAT)/256, 256>>>(wq_b, wqbpk, QLAT/8, QLAT, QW, QW*QLAT);
    pack_b_k<<<(KVBW*KVLAT)/256, 256>>>(wkv_b, wkbpk, KVLAT/8, KVLAT, KVBW, KVBW*KVLAT);
    pack_b_k<<<(DMODEL*OW)/256, 256>>>(wo, wopk, OW/8, OW, DMODEL, DMODEL*OW);
    eta_init_k<<<1, 256>>>();

    // combined GEMM1+3: [16384,1152] K=2048 -> qlatpk + kvapk + kpe(+eta)
    gemm_pk<5><<<dim3(9, 64), 512, GEMM_SMEM>>>(xpk, wqkapk, nullptr, NCOMB, DMODEL, fc);
    // q = q_lat @ wq_b^T  [16384,3072] K=512 -> row-major + silu/rope + eta(0,2)
    gemm_pk<2><<<dim3(24, 64), 512, GEMM_SMEM>>>(qlatpk, wqbpk, q, QW, QLAT, fc);
    // kvb = kv_c @ wkv_b^T  [16384,4096] K=512 -> row-major + silu + eta(1)
    gemm_pk<4><<<dim3(32, 64), 512, GEMM_SMEM>>>(kvapk, wkbpk, kvb, KVBW, KVLAT, nullptr);

    eta_fin_k<<<1, 256>>>();

    attn_kernel<<<dim3(BQ*64, NH), 256>>>();

    // out = attn_out @ wo^T  [16384,2048] K=2048
    gemm_pk<0><<<dim3(16, 64), 512, GEMM_SMEM>>>(attnpk, wopk, out, DMODEL, OW, nullptr);
}

// round 15
// speedup vs baseline: 1.6486x; 1.0139x over previous
#include <cuda_runtime.h>
#include <cuda_bf16.h>
#include <math.h>
#include <float.h>
#include <stdint.h>

// Problem constants
#define BQ      4
#define SEQ     4096
#define DMODEL  2048
#define NH      16
#define DN      128
#define DRD     64
#define DVD     128
#define QLAT    512
#define KVLAT   512
#define MROWS   (BQ*SEQ)          // 16384
#define QW      (NH*(DN+DRD))     // 3072
#define KVAW    (KVLAT+DRD)       // 576
#define KVAP    640               // padded kva width
#define NCOMB   (QLAT+KVAP)       // 1152 combined GEMM1+3 width
#define KVBW    (NH*(DN+DVD))     // 4096
#define OW      (NH*DVD)          // 2048
#define SCALE_F 0.07216878364870323f

// ---------------- scratch ----------------
__device__ float g_q   [MROWS*QW];
__device__ float g_kvb [MROWS*KVBW];
__device__ float g_kpe [MROWS*DRD];
__device__ unsigned int g_eta_enc[256];
__device__ float g_eta[256];
// fragment-packed operands (tf32-rounded)
__device__ float g_xpk   [MROWS*DMODEL];
__device__ float g_qlatpk[MROWS*QLAT];
__device__ float g_kvapk [MROWS*KVLAT];
__device__ float g_attnpk[MROWS*OW];
__device__ float g_wqkapk[NCOMB*DMODEL];    // wq_a tiles then wkv_a tiles
__device__ float g_wqbpk [QW*QLAT];
__device__ float g_wkbpk [KVBW*KVLAT];
__device__ float g_wopk  [DMODEL*OW];

// ---------------- helpers ----------------
__device__ __forceinline__ float silu_f(float x) { return x / (1.0f + expf(-x)); }

__device__ __forceinline__ unsigned encf(float f) {
    unsigned u = __float_as_uint(f);
    return (u & 0x80000000u) ? ~u : (u | 0x80000000u);
}
__device__ __forceinline__ float decf(unsigned u) {
    return (u & 0x80000000u) ? __uint_as_float(u ^ 0x80000000u) : __uint_as_float(~u);
}
__device__ __forceinline__ uint32_t smem_u32(const void* p) {
    uint32_t a;
    asm("{ .reg .u64 t; cvta.to.shared.u64 t, %1; cvt.u32.u64 %0, t; }" : "=r"(a) : "l"(p));
    return a;
}
__device__ __forceinline__ void cpasync16(uint32_t dst, const void* src) {
    asm volatile("cp.async.cg.shared.global [%0], [%1], 16;" :: "r"(dst), "l"(src));
}
__device__ __forceinline__ void cp_commit() { asm volatile("cp.async.commit_group;" ::: "memory"); }
__device__ __forceinline__ void cp_wait2()  { asm volatile("cp.async.wait_group 2;"  ::: "memory"); }

__device__ __forceinline__ uint32_t f2tf(float f) {
    uint32_t r;
    asm("cvt.rna.tf32.f32 %0, %1;" : "=r"(r) : "f"(f));
    return r;
}
__device__ __forceinline__ float f2tff(float f) { return __uint_as_float(f2tf(f)); }

__device__ __forceinline__ void mma8(float* d, const uint32_t* a, const uint32_t* b) {
    asm volatile("mma.sync.aligned.m16n8k8.row.col.f32.tf32.tf32.f32 "
        "{%0,%1,%2,%3},{%4,%5,%6,%7},{%8,%9},{%0,%1,%2,%3};"
        : "+f"(d[0]), "+f"(d[1]), "+f"(d[2]), "+f"(d[3])
        : "r"(a[0]), "r"(a[1]), "r"(a[2]), "r"(a[3]), "r"(b[0]), "r"(b[1]));
}

// packed-A element index: m,k -> offset (Kt = K/8 tiles)
__device__ __forceinline__ size_t a_pk_idx(int m, int k, int Kt) {
    int tm = m >> 4, rr = m & 15, lr = rr & 7, hi = rr >> 3;
    int tk = k >> 3, k7 = k & 7, qk = (k7 >> 2) << 1, lc = k7 & 3;
    return ((size_t)tm * Kt + tk) * 128 + (lr * 4 + lc) * 4 + qk + hi;
}

// ---------------- pack kernels (round to tf32) ----------------
__global__ void pack_a_k(const float* __restrict__ src, float* __restrict__ dst, int Kt, int ld, int n) {
    if (blockIdx.x == 0 && threadIdx.x < 256) g_eta_enc[threadIdx.x] = 0u;   // fused eta init
    int o = blockIdx.x * blockDim.x + threadIdx.x;
    if (o >= n) return;
    int tile = o >> 7, l4q = o & 127, l = l4q >> 2, q = l4q & 3;
    int tm = tile / Kt, tk = tile % Kt;
    int r = tm * 16 + (q & 1) * 8 + (l >> 2);
    int k = tk * 8 + (q >> 1) * 4 + (l & 3);
    dst[o] = f2tff(src[(size_t)r * ld + k]);
}

__global__ void pack_b_k(const float* __restrict__ src, float* __restrict__ dst, int Kt, int ld, int N, int n) {
    int o = blockIdx.x * blockDim.x + threadIdx.x;
    if (o >= n) return;
    int tile = o >> 6, lq = o & 63, l = lq >> 1, q = lq & 1;
    int tn = tile / Kt, tk = tile % Kt;
    int nr = tn * 8 + (l >> 2);
    int k = tk * 8 + q * 4 + (l & 3);
    dst[o] = (nr < N) ? f2tff(src[(size_t)nr * ld + k]) : 0.0f;
}

// ---------------- packed tf32 GEMM: C[M,N] = A[M,K] @ B[N,K]^T ----------------
// BM=256, BN=128, BK=32, 512 threads (16 warps, 64x32 each), 4 stages, 1 CTA/SM.
// EPI: 0=plain  2=Q silu/rope + eta  4=kvb silu + eta
//      5=combined GEMM1+3: cols[0,512) qlat packed, [512,1024) kva packed,
//        [1024,1088) kpe rope+silu+eta, [1088,1152) padding
#define STAGE_B 49152
#define NSTAGE  4
#define GEMM_SMEM (NSTAGE*STAGE_B)     // 192 KB

template<int EPI>
__global__ void __launch_bounds__(512, 1)
gemm_pk(const float* __restrict__ A, const float* __restrict__ B, float* __restrict__ C,
        int N, int K, const float* __restrict__ fc)
{
    extern __shared__ float sm[];
    uint32_t sb = smem_u32(sm);
    int Kt = K >> 3;

    int tid  = threadIdx.x;
    int bm   = blockIdx.y * 256;
    int bn   = blockIdx.x * 128;
    int wid  = tid >> 5, lane = tid & 31;
    int wm   = (wid >> 2) * 64;
    int wn   = (wid & 3) * 32;
    int lr   = lane >> 2, lc = lane & 3;

    float acc[4][4][4];
#pragma unroll
    for (int t = 0; t < 4; t++)
#pragma unroll
        for (int j = 0; j < 4; j++)
#pragma unroll
            for (int v = 0; v < 4; v++) acc[t][j][v] = 0.f;

    auto loadStage = [&](int s, int ko) {
        uint32_t abase = sb + s * STAGE_B;
        uint32_t bbase = abase + 32768;
        int kt0 = ko >> 3;
#pragma unroll
        for (int j = 0; j < 4; j++) {
            int idx = j * 512 + tid;
            int tm = idx >> 7, u = idx & 127;
            const float* src = A + ((size_t)(bm / 16 + tm) * Kt + kt0) * 128 + u * 4;
            cpasync16(abase + tm * 2048 + u * 16, src);
        }
#pragma unroll
        for (int j = 0; j < 2; j++) {
            int idx = j * 512 + tid;
            int tn = idx >> 6, u = idx & 63;
            const float* src = B + ((size_t)(bn / 8 + tn) * Kt + kt0) * 64 + u * 4;
            cpasync16(bbase + tn * 1024 + u * 16, src);
        }
    };

    int nk = K / 32;
    loadStage(0, 0);  cp_commit();
    loadStage(1, 32); cp_commit();
    loadStage(2, 64); cp_commit();

    for (int i = 0; i < nk; i++) {
        int s = i % NSTAGE;
        cp_wait2();
        __syncthreads();
        if (i + 3 < nk) loadStage((i + 3) % NSTAGE, (i + 3) * 32);
        cp_commit();

        const float* as = sm + s * (STAGE_B/4);
        const float* bs = as + 8192;
#pragma unroll
        for (int ks = 0; ks < 4; ks++) {
            uint32_t af[4][4], bf[4][2];
#pragma unroll
            for (int t = 0; t < 4; t++) {
                float4 v = *(const float4*)(as + ((wm >> 4) + t) * 512 + ks * 128 + lane * 4);
                af[t][0] = __float_as_uint(v.x); af[t][1] = __float_as_uint(v.y);
                af[t][2] = __float_as_uint(v.z); af[t][3] = __float_as_uint(v.w);
            }
#pragma unroll
            for (int j = 0; j < 4; j++) {
                float2 v = *(const float2*)(bs + ((wn >> 3) + j) * 256 + ks * 64 + lane * 2);
                bf[j][0] = __float_as_uint(v.x); bf[j][1] = __float_as_uint(v.y);
            }
#pragma unroll
            for (int t = 0; t < 4; t++)
#pragma unroll
                for (int j = 0; j < 4; j++)
                    mma8(acc[t][j], af[t], bf[j]);
        }
    }

    // epilogue (+ optional fused eta max)
    float mnope = -FLT_MAX, mpe = -FLT_MAX;
#pragma unroll
    for (int t = 0; t < 4; t++) {
        int row0 = bm + wm + t * 16 + lr;
#pragma unroll
        for (int j = 0; j < 4; j++) {
            int col = bn + wn + j * 8 + lc * 2;
            float v0 = acc[t][j][0], v1 = acc[t][j][1], v2 = acc[t][j][2], v3 = acc[t][j][3];
            if (EPI == 0) {
                *(float2*)&C[(size_t)row0 * N + col]       = make_float2(v0, v1);
                *(float2*)&C[(size_t)(row0 + 8) * N + col] = make_float2(v2, v3);
            } else if (EPI == 2) {
                int d = col % 192;
                if (d < DN) {
                    v0 = silu_f(v0); v1 = silu_f(v1); v2 = silu_f(v2); v3 = silu_f(v3);
                    mnope = fmaxf(mnope, fmaxf(fmaxf(v0, v1), fmaxf(v2, v3)));
                } else {
                    int p = (d - DN) >> 1;
                    int s0 = row0 & (SEQ - 1), s1 = (row0 + 8) & (SEQ - 1);
                    float c0 = fc[s0*64 + p*2], n0 = fc[s0*64 + p*2 + 1];
                    float c1 = fc[s1*64 + p*2], n1 = fc[s1*64 + p*2 + 1];
                    float r0 = v0*c0 - v1*n0, i0 = v0*n0 + v1*c0;
                    float r1 = v2*c1 - v3*n1, i1 = v2*n1 + v3*c1;
                    v0 = silu_f(r0); v1 = silu_f(i0); v2 = silu_f(r1); v3 = silu_f(i1);
                    mpe = fmaxf(mpe, fmaxf(fmaxf(v0, v1), fmaxf(v2, v3)));
                }
                *(float2*)&C[(size_t)row0 * N + col]       = make_float2(v0, v1);
                *(float2*)&C[(size_t)(row0 + 8) * N + col] = make_float2(v2, v3);
            } else if (EPI == 4) {
                int d = col % 256;
                if (d < DN) {
                    v0 = silu_f(v0); v1 = silu_f(v1); v2 = silu_f(v2); v3 = silu_f(v3);
                    mnope = fmaxf(mnope, fmaxf(fmaxf(v0, v1), fmaxf(v2, v3)));
                }
                *(float2*)&C[(size_t)row0 * N + col]       = make_float2(v0, v1);
                *(float2*)&C[(size_t)(row0 + 8) * N + col] = make_float2(v2, v3);
            } else if (EPI == 5) {
                int tm = (bm + wm + t * 16) >> 4;
                if (col < QLAT) {
                    int tk = col >> 3;
                    int lp = lr * 4 + ((col & 7) & 3);
                    int qk = (col & 4) >> 1;
                    size_t base = ((size_t)tm * 64 + tk) * 128;
                    *(float2*)&g_qlatpk[base + lp * 4 + qk]       = make_float2(f2tff(v0), f2tff(v2));
                    *(float2*)&g_qlatpk[base + (lp + 1) * 4 + qk] = make_float2(f2tff(v1), f2tff(v3));
                } else {
                    int col2 = col - QLAT;
                    if (col2 < KVLAT) {
                        int tk = col2 >> 3;
                        int lp = lr * 4 + ((col2 & 7) & 3);
                        int qk = (col2 & 4) >> 1;
                        size_t base = ((size_t)tm * 64 + tk) * 128;
                        *(float2*)&g_kvapk[base + lp * 4 + qk]       = make_float2(f2tff(v0), f2tff(v2));
                        *(float2*)&g_kvapk[base + (lp + 1) * 4 + qk] = make_float2(f2tff(v1), f2tff(v3));
                    } else if (col2 < KVAW) {
                        int d = col2 - KVLAT;
                        int p = d >> 1;
                        int s0 = row0 & (SEQ - 1), s1 = (row0 + 8) & (SEQ - 1);
                        float c0 = fc[s0*64 + p*2], n0 = fc[s0*64 + p*2 + 1];
                        float c1 = fc[s1*64 + p*2], n1 = fc[s1*64 + p*2 + 1];
                        float y00 = silu_f(v0*c0 - v1*n0);
                        float y01 = silu_f(v0*n0 + v1*c0);
                        float y10 = silu_f(v2*c1 - v3*n1);
                        float y11 = silu_f(v2*n1 + v3*c1);
                        *(float2*)&g_kpe[(size_t)row0 * DRD + d]       = make_float2(y00, y01);
                        *(float2*)&g_kpe[(size_t)(row0 + 8) * DRD + d] = make_float2(y10, y11);
                        mpe = fmaxf(mpe, fmaxf(fmaxf(y00, y01), fmaxf(y10, y11)));
                    }
                }
            }
        }
    }

    if (EPI == 2 || EPI == 4 || EPI == 5) {
        __syncthreads();
        sm[tid] = mnope;
        sm[512 + tid] = mpe;
        __syncthreads();
        for (int st = 256; st > 0; st >>= 1) {
            if (tid < st) {
                sm[tid] = fmaxf(sm[tid], sm[tid + st]);
                sm[512 + tid] = fmaxf(sm[512 + tid], sm[512 + tid + st]);
            }
            __syncthreads();
        }
        if (tid == 0) {
            int grp = bm >> 8;
            if (EPI == 2) {
                atomicMax(&g_eta_enc[grp], encf(sm[0]));
                atomicMax(&g_eta_enc[128 + grp], encf(sm[512]));
            } else if (EPI == 4) {
                atomicMax(&g_eta_enc[64 + grp], encf(sm[0]));
            } else if (EPI == 5) {
                if (blockIdx.x == 8)
                    atomicMax(&g_eta_enc[192 + grp], encf(sm[512]));
            }
        }
    }
}

// ---------------- eta finalize ----------------
__global__ void eta_fin_k() {
    int i = threadIdx.x;
    if (i < 256) {
        float m = decf(g_eta_enc[i]);
        if (m == 0.0f) m = 1e-6f;
        g_eta[i] = fminf(10.0f / m, 1.0f);
    }
}

// ---------------- block attention (output packed for GEMM5 A) ----------------
__global__ void __launch_bounds__(256) attn_kernel() {
    __shared__ float sA[64*65];
    __shared__ float sB[64*65];
    int bnb = blockIdx.x;
    int h   = blockIdx.y;
    int b = bnb >> 6, n = bnb & 63;
    int m0 = b*SEQ + n*64;
    int tid = threadIdx.x;
    int ty = tid >> 4, tx = tid & 15;

    float eqn = g_eta[  0 + b*16 + h];
    float ekn = g_eta[ 64 + b*16 + h];
    float eqp = g_eta[128 + b*16 + h];
    float ekp = g_eta[192 + b*16 + h];

    float c_pe[4][4], c_np[4][4];
#pragma unroll
    for (int i = 0; i < 4; i++)
#pragma unroll
        for (int j = 0; j < 4; j++) { c_pe[i][j] = 0.f; c_np[i][j] = 0.f; }

    for (int idx = tid; idx < 4096; idx += 256) {
        int q = idx >> 6, d = idx & 63;
        sA[d*65 + q] = g_q[(size_t)(m0+q)*QW + h*192 + DN + d];
        sB[d*65 + q] = g_kpe[(size_t)(m0+q)*DRD + d];
    }
    __syncthreads();
#pragma unroll 4
    for (int k = 0; k < 64; k++) {
        float a[4], bb[4];
#pragma unroll
        for (int i = 0; i < 4; i++) a[i]  = sA[k*65 + ty*4 + i];
#pragma unroll
        for (int j = 0; j < 4; j++) bb[j] = sB[k*65 + tx*4 + j];
#pragma unroll
        for (int i = 0; i < 4; i++)
#pragma unroll
            for (int j = 0; j < 4; j++)
                c_pe[i][j] = fmaf(a[i], bb[j], c_pe[i][j]);
    }
    __syncthreads();

    for (int ch = 0; ch < 2; ch++) {
        for (int idx = tid; idx < 4096; idx += 256) {
            int q = idx >> 6, d = idx & 63;
            sA[d*65 + q] = g_q  [(size_t)(m0+q)*QW   + h*192 + ch*64 + d];
            sB[d*65 + q] = g_kvb[(size_t)(m0+q)*KVBW + h*256 + ch*64 + d];
        }
        __syncthreads();
#pragma unroll 4
        for (int k = 0; k < 64; k++) {
            float a[4], bb[4];
#pragma unroll
            for (int i = 0; i < 4; i++) a[i]  = sA[k*65 + ty*4 + i];
#pragma unroll
            for (int j = 0; j < 4; j++) bb[j] = sB[k*65 + tx*4 + j];
#pragma unroll
            for (int i = 0; i < 4; i++)
#pragma unroll
                for (int j = 0; j < 4; j++)
                    c_np[i][j] = fmaf(a[i], bb[j], c_np[i][j]);
        }
        __syncthreads();
    }

    float fn = eqn * ekn * SCALE_F;
    float fp = eqp * ekp * SCALE_F;
#pragma unroll
    for (int i = 0; i < 4; i++)
#pragma unroll
        for (int j = 0; j < 4; j++) {
            int q = ty*4 + i, kk = tx*4 + j;
            float v = c_np[i][j]*fn + c_pe[i][j]*fp;
            if (kk > q) v = -3.402823466e38f;
            sA[q*65 + kk] = v;
        }
    __syncthreads();

    {
        int w = tid >> 5, lane = tid & 31;
        for (int r = w; r < 64; r += 8) {
            float x0 = sA[r*65 + lane];
            float x1 = sA[r*65 + lane + 32];
            float mx = fmaxf(x0, x1);
#pragma unroll
            for (int o = 16; o > 0; o >>= 1)
                mx = fmaxf(mx, __shfl_xor_sync(0xffffffffu, mx, o));
            float e0 = expf(x0 - mx);
            float e1 = expf(x1 - mx);
            float sm = e0 + e1;
#pragma unroll
            for (int o = 16; o > 0; o >>= 1)
                sm += __shfl_xor_sync(0xffffffffu, sm, o);
            float inv = 1.0f / sm;
            sA[r*65 + lane]      = e0 * inv;
            sA[r*65 + lane + 32] = e1 * inv;
        }
    }
    __syncthreads();

    for (int ch = 0; ch < 2; ch++) {
        for (int idx = tid; idx < 4096; idx += 256) {
            int kk = idx >> 6, d = idx & 63;
            sB[kk*65 + d] = g_kvb[(size_t)(m0+kk)*KVBW + h*256 + DN + ch*64 + d];
        }
        __syncthreads();
        float o[4][4];
#pragma unroll
        for (int i = 0; i < 4; i++)
#pragma unroll
            for (int j = 0; j < 4; j++) o[i][j] = 0.f;
#pragma unroll 4
        for (int k = 0; k < 64; k++) {
            float a[4], bb[4];
#pragma unroll
            for (int i = 0; i < 4; i++) a[i]  = sA[(ty*4 + i)*65 + k];
#pragma unroll
            for (int j = 0; j < 4; j++) bb[j] = sB[k*65 + tx*4 + j];
#pragma unroll
            for (int i = 0; i < 4; i++)
#pragma unroll
                for (int j = 0; j < 4; j++)
                    o[i][j] = fmaf(a[i], bb[j], o[i][j]);
        }
#pragma unroll
        for (int i = 0; i < 4; i++) {
            int m = m0 + ty*4 + i;
            int kk0 = h*DVD + ch*64 + tx*4;
#pragma unroll
            for (int j = 0; j < 4; j++)
                g_attnpk[a_pk_idx(m, kk0 + j, 256)] = f2tff(o[i][j]);
        }
        __syncthreads();
    }
}

// ---------------- launch ----------------
extern "C" void kernel_launch(void* const* d_in, const int* in_sizes, int n_in,
                              void* d_out, int out_size)
{
    const float* x     = (const float*)d_in[0];
    const float* fc    = (const float*)d_in[1];
    const float* wq_a  = (const float*)d_in[2];
    const float* wq_b  = (const float*)d_in[3];
    const float* wkv_a = (const float*)d_in[4];
    const float* wkv_b = (const float*)d_in[5];
    const float* wo    = (const float*)d_in[6];
    float* out = (float*)d_out;

    float *q, *kvb;
    float *xpk, *qlatpk, *kvapk, *attnpk;
    float *wqkapk, *wqbpk, *wkbpk, *wopk;
    cudaGetSymbolAddress((void**)&q,      g_q);
    cudaGetSymbolAddress((void**)&kvb,    g_kvb);
    cudaGetSymbolAddress((void**)&xpk,    g_xpk);
    cudaGetSymbolAddress((void**)&qlatpk, g_qlatpk);
    cudaGetSymbolAddress((void**)&kvapk,  g_kvapk);
    cudaGetSymbolAddress((void**)&attnpk, g_attnpk);
    cudaGetSymbolAddress((void**)&wqkapk, g_wqkapk);
    cudaGetSymbolAddress((void**)&wqbpk,  g_wqbpk);
    cudaGetSymbolAddress((void**)&wkbpk,  g_wkbpk);
    cudaGetSymbolAddress((void**)&wopk,   g_wopk);

    cudaFuncSetAttribute(gemm_pk<0>, cudaFuncAttributeMaxDynamicSharedMemorySize, GEMM_SMEM);
    cudaFuncSetAttribute(gemm_pk<2>, cudaFuncAttributeMaxDynamicSharedMemorySize, GEMM_SMEM);
    cudaFuncSetAttribute(gemm_pk<4>, cudaFuncAttributeMaxDynamicSharedMemorySize, GEMM_SMEM);
    cudaFuncSetAttribute(gemm_pk<5>, cudaFuncAttributeMaxDynamicSharedMemorySize, GEMM_SMEM);

    // launches 0-4 (pack_a also zeroes eta_enc)
    pack_a_k<<<(MROWS*DMODEL)/256, 256>>>(x, xpk, DMODEL/8, DMODEL, MROWS*DMODEL);
    pack_b_k<<<(QLAT*DMODEL)/256, 256>>>(wq_a, wqkapk, DMODEL/8, DMODEL, QLAT, QLAT*DMODEL);
    pack_b_k<<<(KVAP*DMODEL)/256, 256>>>(wkv_a, wqkapk + (size_t)QLAT*DMODEL, DMODEL/8, DMODEL, KVAW, KVAP*DMODEL);
    pack_b_k<<<(QW*QLAT)/256, 256>>>(wq_b, wqbpk, QLAT/8, QLAT, QW, QW*QLAT);
    pack_b_k<<<(KVBW*KVLAT)/256, 256>>>(wkv_b, wkbpk, KVLAT/8, KVLAT, KVBW, KVBW*KVLAT);

    // launch 5 (ncu profiles this): combined GEMM1+3 [16384,1152] K=2048
    gemm_pk<5><<<dim3(9, 64), 512, GEMM_SMEM>>>(xpk, wqkapk, nullptr, NCOMB, DMODEL, fc);
    // q = q_lat @ wq_b^T  [16384,3072] K=512 -> row-major + silu/rope + eta(0,2)
    gemm_pk<2><<<dim3(24, 64), 512, GEMM_SMEM>>>(qlatpk, wqbpk, q, QW, QLAT, fc);
    // kvb = kv_c @ wkv_b^T  [16384,4096] K=512 -> row-major + silu + eta(1)
    gemm_pk<4><<<dim3(32, 64), 512, GEMM_SMEM>>>(kvapk, wkbpk, kvb, KVBW, KVLAT, nullptr);

    eta_fin_k<<<1, 256>>>();

    attn_kernel<<<dim3(BQ*64, NH), 256>>>();

    pack_b_k<<<(DMODEL*OW)/256, 256>>>(wo, wopk, OW/8, OW, DMODEL, DMODEL*OW);
    // out = attn_out @ wo^T  [16384,2048] K=2048
    gemm_pk<0><<<dim3(16, 64), 512, GEMM_SMEM>>>(attnpk, wopk, out, DMODEL, OW, nullptr);
}